// round 6
// baseline (speedup 1.0000x reference)
#include <cuda_runtime.h>
#include <cuda_fp16.h>
#include <math.h>
#include <stdint.h>

// Problem constants
#define Bn 2
#define Sn 1024
#define Dn 1024
#define NHn 16
#define HDn 64
#define En 8
#define HIDn 4096
#define Tn (Bn*Sn)          // 2048 tokens
#define MAXROWS 5248        // >= 4096 assignments + 8*127 padding, mult of 128

// ---------------- scratch (static device globals; no allocation) -------------
static __device__ __half g_XNh [Tn*Dn];
static __device__ float  g_Qb  [Tn*Dn];
static __device__ float  g_Kb  [Tn*Dn];
static __device__ float  g_Vb  [Tn*Dn];
static __device__ __half g_ATTh[Tn*Dn];
static __device__ float  g_Hb  [Tn*Dn];
static __device__ float  g_XN2 [Tn*Dn];
static __device__ __half g_XN2h[Tn*Dn];
static __device__ float  g_GBUF[(size_t)MAXROWS*HIDn];
static __device__ float  g_UBUF[(size_t)MAXROWS*HIDn];
static __device__ __half g_Hh  [(size_t)MAXROWS*HIDn];
// fp16 weights
static __device__ __half g_Wqh[Dn*Dn];
static __device__ __half g_Wkh[Dn*Dn];
static __device__ __half g_Wvh[Dn*Dn];
static __device__ __half g_Woh[Dn*Dn];
static __device__ __half g_Wgeh[(size_t)En*HIDn*Dn];
static __device__ __half g_Wueh[(size_t)En*HIDn*Dn];
static __device__ __half g_Wdeh[(size_t)En*Dn*HIDn];
// routing
static __device__ int   g_cnt[En];
static __device__ int   g_cursor[En];
static __device__ int   g_rowtok[MAXROWS];
static __device__ int   g_rowexp[MAXROWS];
static __device__ float g_rowgate[MAXROWS];
static __device__ int   g_totalrows;
static __device__ float g_gsum[En];
static __device__ float g_psum[En];
static __device__ int   g_expid[Tn*2];
static __device__ float g_gateval[Tn*2];

// ======================= PTX helpers =========================================
static __device__ __forceinline__ uint32_t smem_u32_(const void* p){
    uint32_t a;
    asm("{ .reg .u64 t; cvta.to.shared.u64 t, %1; cvt.u32.u64 %0, t; }"
        : "=r"(a) : "l"(p));
    return a;
}

#define LDSM_X4(r0,r1,r2,r3,addr) \
    asm volatile("ldmatrix.sync.aligned.m8n8.x4.shared.b16 {%0,%1,%2,%3}, [%4];" \
        : "=r"(r0),"=r"(r1),"=r"(r2),"=r"(r3) : "r"(addr))

#define MMA16816(c,a,b) \
    asm volatile("mma.sync.aligned.m16n8k16.row.col.f32.f16.f16.f32 " \
        "{%0,%1,%2,%3}, {%4,%5,%6,%7}, {%8,%9}, {%0,%1,%2,%3};" \
        : "+f"((c)[0]),"+f"((c)[1]),"+f"((c)[2]),"+f"((c)[3]) \
        : "r"((a)[0]),"r"((a)[1]),"r"((a)[2]),"r"((a)[3]), \
          "r"((b)[0]),"r"((b)[1]))

#define CP_COMMIT() asm volatile("cp.async.commit_group;" ::: "memory")
#define CP_WAIT1()  asm volatile("cp.async.wait_group 1;" ::: "memory")
#define CP_WAIT0()  asm volatile("cp.async.wait_group 0;" ::: "memory")

static __device__ __forceinline__ void cp16_(uint32_t dst, const void* src, int srcsize){
    asm volatile("cp.async.cg.shared.global [%0], [%1], 16, %2;"
        :: "r"(dst), "l"((unsigned long long)__cvta_generic_to_global(src)),
           "r"(srcsize) : "memory");
}

// ============================== small kernels ================================
__global__ void k_reset() {
    int i = threadIdx.x;
    if (i < En) { g_cnt[i] = 0; g_gsum[i] = 0.f; g_psum[i] = 0.f; }
}

// fp32 -> fp16, 4 x float4 per thread, grid-stride
__global__ void k_f2h(const float4* __restrict__ s, uint2* __restrict__ d, int n4){
    int stride = gridDim.x * blockDim.x;
    for (int i = blockIdx.x*blockDim.x + threadIdx.x; i < n4; i += stride){
        float4 v = s[i];
        __half2 h0 = __floats2half2_rn(v.x, v.y);
        __half2 h1 = __floats2half2_rn(v.z, v.w);
        uint2 o;
        o.x = *reinterpret_cast<uint32_t*>(&h0);
        o.y = *reinterpret_cast<uint32_t*>(&h1);
        d[i] = o;
    }
}

__global__ void k_rmsnorm(const float* __restrict__ x, const float* __restrict__ w,
                          float* __restrict__ y, __half* __restrict__ yh) {
    int t = blockIdx.x;
    const float* xr = x + (size_t)t * Dn;
    int base = threadIdx.x * 4;
    float4 xv = *(const float4*)(xr + base);
    float ss = xv.x*xv.x + xv.y*xv.y + xv.z*xv.z + xv.w*xv.w;
    #pragma unroll
    for (int o = 16; o; o >>= 1) ss += __shfl_xor_sync(0xffffffffu, ss, o);
    __shared__ float ws[8];
    if ((threadIdx.x & 31) == 0) ws[threadIdx.x >> 5] = ss;
    __syncthreads();
    float tot = ws[0]+ws[1]+ws[2]+ws[3]+ws[4]+ws[5]+ws[6]+ws[7];
    float sc = rsqrtf(tot * (1.f/(float)Dn) + 1e-6f);
    float4 wv = *(const float4*)(w + base);
    float4 o4;
    o4.x = wv.x*xv.x*sc; o4.y = wv.y*xv.y*sc;
    o4.z = wv.z*xv.z*sc; o4.w = wv.w*xv.w*sc;
    if (y) *(float4*)(y + (size_t)t*Dn + base) = o4;
    __half2 h0 = __floats2half2_rn(o4.x, o4.y);
    __half2 h1 = __floats2half2_rn(o4.z, o4.w);
    uint2 ho;
    ho.x = *reinterpret_cast<uint32_t*>(&h0);
    ho.y = *reinterpret_cast<uint32_t*>(&h1);
    *(uint2*)(yh + (size_t)t*Dn + base) = ho;
}

// ===================== mma.sync GEMM (HMMA tensor path) ======================
// C[128*mt.., 128*nt..] = A(fp16,lda) @ B(fp16,ldb)^T, fp32 accum.
// Tile 128x128x64, 3-stage cp.async, ONE __syncthreads per K-stage.
#define EPI_PLAIN 0
#define EPI_RESID 1
#define EPI_DOWN  2
#define GEMM_SMEM (3*32768)

template<int NITER, int EPI, bool GATHER, bool ESEL>
__global__ __launch_bounds__(256)
void k_gemm(const __half* __restrict__ A0, int lda,
            const __half* __restrict__ B0, const __half* __restrict__ B1,
            const __half* __restrict__ B2,
            long bstride, int ldb,
            float* __restrict__ C0, float* __restrict__ C1c, float* __restrict__ C2c,
            int ldc,
            const float* __restrict__ resid, float* __restrict__ Cdual)
{
    int mt = blockIdx.y, nt = blockIdx.x;
    if (ESEL && mt*128 >= g_totalrows) return;
    const __half* Bh = (blockIdx.z==0) ? B0 : ((blockIdx.z==1) ? B1 : B2);
    float* C = (blockIdx.z==0) ? C0 : ((blockIdx.z==1) ? C1c : C2c);
    if (ESEL) Bh += (long)g_rowexp[mt*128] * bstride;

    extern __shared__ __align__(128) char sm_[];
    uint32_t sbase = smem_u32_(sm_);

    int tid = threadIdx.x, lane = tid & 31, wid = tid >> 5;
    int warp_m = wid & 3, warp_n = wid >> 2;

    // staging: row = tid/2 (128 rows), each thread owns 4 16B fp16 chunks
    int lrow = tid >> 1;
    int lc0  = (tid & 1) * 4;
    const __half* asrc;
    bool avalid = true;
    if (GATHER){
        int tok = g_rowtok[mt*128 + lrow];
        avalid = (tok >= 0);
        asrc = A0 + (avalid ? (size_t)tok * lda : 0);
    } else {
        asrc = A0 + (size_t)(mt*128 + lrow) * lda;
    }
    const __half* bsrc = Bh + (size_t)(nt*128 + lrow) * ldb;
    int asz = avalid ? 16 : 0;

    uint32_t soff[4];
    #pragma unroll
    for (int i = 0; i < 4; i++){
        int c = lc0 + i;
        soff[i] = (uint32_t)(lrow*128 + ((c ^ (lrow & 7)) * 16));
    }

    auto stg = [&](int it){
        uint32_t so = (uint32_t)(it % 3) * 32768u;
        const char* ag = (const char*)(asrc + it*64);
        const char* bg = (const char*)(bsrc + it*64);
        #pragma unroll
        for (int i = 0; i < 4; i++){
            cp16_(sbase + so + soff[i], ag + (lc0+i)*16, asz);
            cp16_(sbase + so + 16384u + soff[i], bg + (lc0+i)*16, 16);
        }
    };

    float acc[2][8][4];
    #pragma unroll
    for (int i=0;i<2;i++)
        #pragma unroll
        for (int j=0;j<8;j++)
            #pragma unroll
            for (int k=0;k<4;k++) acc[i][j][k]=0.f;

    int a_rlo = (lane & 15);
    int a_chk = (lane >> 4);
    int b_rlo = (lane & 7) + ((lane & 16) ? 8 : 0);
    int b_chk = (lane >> 3) & 1;

    // prologue: 2 stages in flight
    stg(0); CP_COMMIT();
    stg(1); CP_COMMIT();

    for (int it = 0; it < NITER; it++){
        CP_WAIT1();
        __syncthreads();
        if (it + 2 < NITER){ stg(it + 2); CP_COMMIT(); }
        else { CP_COMMIT(); }   // keep group accounting uniform

        uint32_t abase = sbase + (uint32_t)(it % 3) * 32768u;
        uint32_t bbase = abase + 16384u;
        #pragma unroll
        for (int ks = 0; ks < 4; ks++){
            uint32_t a[2][4];
            #pragma unroll
            for (int mtile = 0; mtile < 2; mtile++){
                int row = warp_m*32 + mtile*16 + a_rlo;
                int chunk = 2*ks + a_chk;
                uint32_t addr = abase + row*128 + ((chunk ^ (row & 7)) * 16);
                LDSM_X4(a[mtile][0], a[mtile][1], a[mtile][2], a[mtile][3], addr);
            }
            uint32_t b[8][2];
            #pragma unroll
            for (int n2 = 0; n2 < 4; n2++){
                int row = warp_n*64 + n2*16 + b_rlo;
                int chunk = 2*ks + b_chk;
                uint32_t addr = bbase + row*128 + ((chunk ^ (row & 7)) * 16);
                uint32_t r0,r1,r2,r3;
                LDSM_X4(r0, r1, r2, r3, addr);
                b[2*n2][0]=r0; b[2*n2][1]=r1;
                b[2*n2+1][0]=r2; b[2*n2+1][1]=r3;
            }
            #pragma unroll
            for (int mtile = 0; mtile < 2; mtile++)
                #pragma unroll
                for (int n8 = 0; n8 < 8; n8++)
                    MMA16816(acc[mtile][n8], a[mtile], b[n8]);
        }
    }
    CP_WAIT0();

    // ---- epilogue ----
    int m0 = mt*128 + warp_m*32;
    int n0 = nt*128 + warp_n*64;
    int gq = lane >> 2, tq = lane & 3;
    #pragma unroll
    for (int mtile = 0; mtile < 2; mtile++){
        int r_lo = m0 + mtile*16 + gq;
        int r_hi = r_lo + 8;
        if (EPI == EPI_DOWN){
            int tok_lo = g_rowtok[r_lo], tok_hi = g_rowtok[r_hi];
            float gl = g_rowgate[r_lo], gh = g_rowgate[r_hi];
            #pragma unroll
            for (int n8 = 0; n8 < 8; n8++){
                int col = n0 + n8*8 + tq*2;
                if (tok_lo >= 0){
                    size_t o = (size_t)tok_lo*ldc + col;
                    atomicAdd(&C[o],   gl*acc[mtile][n8][0]);
                    atomicAdd(&C[o+1], gl*acc[mtile][n8][1]);
                }
                if (tok_hi >= 0){
                    size_t o = (size_t)tok_hi*ldc + col;
                    atomicAdd(&C[o],   gh*acc[mtile][n8][2]);
                    atomicAdd(&C[o+1], gh*acc[mtile][n8][3]);
                }
            }
        } else if (EPI == EPI_RESID){
            #pragma unroll
            for (int n8 = 0; n8 < 8; n8++){
                int col = n0 + n8*8 + tq*2;
                size_t o_lo = (size_t)r_lo*ldc + col;
                size_t o_hi = (size_t)r_hi*ldc + col;
                float2 rv0 = *(const float2*)(resid + o_lo);
                float2 rv1 = *(const float2*)(resid + o_hi);
                float2 v0, v1;
                v0.x = acc[mtile][n8][0] + rv0.x;
                v0.y = acc[mtile][n8][1] + rv0.y;
                v1.x = acc[mtile][n8][2] + rv1.x;
                v1.y = acc[mtile][n8][3] + rv1.y;
                *(float2*)(C + o_lo) = v0;
                *(float2*)(C + o_hi) = v1;
                *(float2*)(Cdual + o_lo) = v0;
                *(float2*)(Cdual + o_hi) = v1;
            }
        } else {
            #pragma unroll
            for (int n8 = 0; n8 < 8; n8++){
                int col = n0 + n8*8 + tq*2;
                float2 v0, v1;
                v0.x = acc[mtile][n8][0]; v0.y = acc[mtile][n8][1];
                v1.x = acc[mtile][n8][2]; v1.y = acc[mtile][n8][3];
                *(float2*)(C + (size_t)r_lo*ldc + col) = v0;
                *(float2*)(C + (size_t)r_hi*ldc + col) = v1;
            }
        }
    }
}

// ============================ RoPE / attention ===============================
// One launch: blockIdx.y==0 -> Q, ==1 -> K
__global__ void k_rope(float* __restrict__ q, float* __restrict__ kk) {
    int idx = blockIdx.x*blockDim.x + threadIdx.x;
    if (idx >= Tn*NHn*32) return;
    float* dst = blockIdx.y ? kk : q;
    int i = idx & 31;
    int t = idx >> 9;
    int h = (idx >> 5) & (NHn-1);
    int s = t & (Sn-1);
    float invf = __powf(10000.f, -((float)(2*i)) * (1.f/(float)HDn));
    float fr = (float)s * invf;
    float c, sn;
    __sincosf(fr, &sn, &c);
    float* p = dst + (size_t)t*Dn + h*HDn + i;
    float v1 = p[0], v2 = p[32];
    p[0]  = v1*c - v2*sn;
    p[32] = v2*c + v1*sn;
}

__global__ __launch_bounds__(256)
void k_attn(const float* __restrict__ Q, const float* __restrict__ Kg,
            const float* __restrict__ V, __half* __restrict__ O)
{
    __shared__ float Qs [64*64];
    __shared__ float KVs[64*64];
    __shared__ float Ps [64*64];
    int bh = blockIdx.x;
    int qt = blockIdx.y;
    int b = bh >> 4, h = bh & 15;
    int tid = threadIdx.x;
    int ty = tid >> 4, tx = tid & 15;
    size_t base = ((size_t)b*Sn)*Dn + (size_t)h*HDn;
    int q0 = qt*64;
    #pragma unroll
    for (int rep=0;rep<4;rep++){
        int lin = tid + rep*256;
        int r = lin >> 4, c = (lin & 15)*4;
        *(float4*)&Qs[r*64+c] = *(const float4*)(Q + base + (size_t)(q0+r)*Dn + c);
    }
    float acc[4][4];
    float mrow[4], lrow[4];
    #pragma unroll
    for (int i=0;i<4;i++){
        mrow[i] = -1e30f; lrow[i] = 0.f;
        #pragma unroll
        for (int j=0;j<4;j++) acc[i][j]=0.f;
    }
    __syncthreads();
    for (int kt=0; kt<=qt; kt++){
        int k0 = kt*64;
        #pragma unroll
        for (int rep=0;rep<4;rep++){
            int lin = tid + rep*256;
            int r = lin >> 4, c = (lin & 15)*4;
            float4 kv = *(const float4*)(Kg + base + (size_t)(k0+r)*Dn + c);
            KVs[(c+0)*64 + r] = kv.x;
            KVs[(c+1)*64 + r] = kv.y;
            KVs[(c+2)*64 + r] = kv.z;
            KVs[(c+3)*64 + r] = kv.w;
        }
        __syncthreads();
        float s[4][4];
        #pragma unroll
        for (int i=0;i<4;i++)
            #pragma unroll
            for (int j=0;j<4;j++) s[i][j]=0.f;
        #pragma unroll 4
        for (int d=0; d<64; d++){
            float qa[4], kb[4];
            #pragma unroll
            for (int i=0;i<4;i++) qa[i] = Qs[(ty*4+i)*64 + d];
            #pragma unroll
            for (int j=0;j<4;j++) kb[j] = KVs[d*64 + tx*4 + j];
            #pragma unroll
            for (int i=0;i<4;i++)
                #pragma unroll
                for (int j=0;j<4;j++) s[i][j] = fmaf(qa[i], kb[j], s[i][j]);
        }
        #pragma unroll
        for (int i=0;i<4;i++){
            int qq = q0 + ty*4 + i;
            #pragma unroll
            for (int j=0;j<4;j++){
                int kk = k0 + tx*4 + j;
                s[i][j] = (kk <= qq) ? s[i][j]*0.125f : -1e30f;
            }
        }
        #pragma unroll
        for (int i=0;i<4;i++){
            float mt = fmaxf(fmaxf(s[i][0],s[i][1]), fmaxf(s[i][2],s[i][3]));
            #pragma unroll
            for (int o=8;o;o>>=1) mt = fmaxf(mt, __shfl_xor_sync(0xffffffffu, mt, o));
            float mn = fmaxf(mrow[i], mt);
            float corr = __expf(mrow[i] - mn);
            float rs = 0.f;
            #pragma unroll
            for (int j=0;j<4;j++){ float p = __expf(s[i][j]-mn); s[i][j]=p; rs+=p; }
            #pragma unroll
            for (int o=8;o;o>>=1) rs += __shfl_xor_sync(0xffffffffu, rs, o);
            lrow[i] = lrow[i]*corr + rs;
            mrow[i] = mn;
            #pragma unroll
            for (int j=0;j<4;j++) acc[i][j] *= corr;
            #pragma unroll
            for (int j=0;j<4;j++) Ps[(ty*4+i)*64 + tx*4+j] = s[i][j];
        }
        __syncthreads();
        #pragma unroll
        for (int rep=0;rep<4;rep++){
            int lin = tid + rep*256;
            int r = lin >> 4, c = (lin & 15)*4;
            *(float4*)&KVs[r*64+c] = *(const float4*)(V + base + (size_t)(k0+r)*Dn + c);
        }
        __syncthreads();
        #pragma unroll 4
        for (int kv=0; kv<64; kv++){
            float pv[4], vv[4];
            #pragma unroll
            for (int i=0;i<4;i++) pv[i] = Ps[(ty*4+i)*64 + kv];
            #pragma unroll
            for (int j=0;j<4;j++) vv[j] = KVs[kv*64 + tx*4 + j];
            #pragma unroll
            for (int i=0;i<4;i++)
                #pragma unroll
                for (int j=0;j<4;j++) acc[i][j] = fmaf(pv[i], vv[j], acc[i][j]);
        }
        __syncthreads();
    }
    #pragma unroll
    for (int i=0;i<4;i++){
        float inv = 1.f/lrow[i];
        size_t o = base + (size_t)(q0+ty*4+i)*Dn + tx*4;
        __half2 p0 = __floats2half2_rn(acc[i][0]*inv, acc[i][1]*inv);
        __half2 p1 = __floats2half2_rn(acc[i][2]*inv, acc[i][3]*inv);
        *(__half2*)(O + o)     = p0;
        *(__half2*)(O + o + 2) = p1;
    }
}

// =============================== gating / MoE ================================
__global__ void k_gate(const float* __restrict__ xn, const float* __restrict__ gw)
{
    int t = blockIdx.x;
    int w = threadIdx.x >> 5, lane = threadIdx.x & 31;
    const float* xr = xn + (size_t)t * Dn;
    const float* gr = gw + (size_t)w * Dn;
    float acc = 0.f;
    for (int d = lane; d < Dn; d += 32) acc = fmaf(xr[d], gr[d], acc);
    #pragma unroll
    for (int o=16;o;o>>=1) acc += __shfl_xor_sync(0xffffffffu, acc, o);
    __shared__ float lg[En];
    if (lane == 0) lg[w] = acc;
    __syncthreads();
    if (threadIdx.x == 0){
        int i1 = 0;
        for (int e=1;e<En;e++) if (lg[e] > lg[i1]) i1 = e;
        int i2 = -1;
        for (int e=0;e<En;e++){
            if (e == i1) continue;
            if (i2 < 0 || lg[e] > lg[i2]) i2 = e;
        }
        float l1 = lg[i1], l2 = lg[i2];
        float e2 = expf(l2 - l1);
        float inv = 1.f/(1.f + e2);
        float gv1 = inv, gv2 = e2*inv;
        g_expid[t*2]   = i1; g_expid[t*2+1]   = i2;
        g_gateval[t*2] = gv1; g_gateval[t*2+1] = gv2;
        atomicAdd(&g_cnt[i1], 1); atomicAdd(&g_cnt[i2], 1);
        atomicAdd(&g_gsum[i1], gv1); atomicAdd(&g_gsum[i2], gv2);
        float mx = lg[0];
        for (int e=1;e<En;e++) mx = fmaxf(mx, lg[e]);
        float pe[En]; float se = 0.f;
        for (int e=0;e<En;e++){ pe[e] = expf(lg[e]-mx); se += pe[e]; }
        float pinv = 1.f/se;
        for (int e=0;e<En;e++) atomicAdd(&g_psum[e], pe[e]*pinv);
    }
}

__global__ void k_offsets(float* __restrict__ out, int write_aux)
{
    __shared__ int soff[En+1];
    if (threadIdx.x == 0){
        int tot = 0;
        for (int e=0;e<En;e++){
            soff[e] = tot;
            g_cursor[e] = tot;
            tot += ((g_cnt[e] + 127) >> 7) << 7;
        }
        soff[En] = tot;
        g_totalrows = tot;
        if (write_aux){
            float sacc = 0.f;
            for (int e=0;e<En;e++) sacc += g_gsum[e]*g_psum[e];
            out[(size_t)Tn*Dn] = (float)En * sacc / ((float)Tn*(float)Tn);
        }
    }
    __syncthreads();
    int tot = soff[En];
    for (int r = threadIdx.x; r < tot; r += blockDim.x){
        int e = 0;
        while (e+1 < En && r >= soff[e+1]) e++;
        g_rowexp[r] = e;
        g_rowtok[r] = -1;
    }
}

__global__ void k_scatter()
{
    int t = blockIdx.x*blockDim.x + threadIdx.x;
    if (t >= Tn) return;
    #pragma unroll
    for (int k=0;k<2;k++){
        int e = g_expid[t*2+k];
        int pos = atomicAdd(&g_cursor[e], 1);
        g_rowtok[pos] = t;
        g_rowgate[pos] = g_gateval[t*2+k];
    }
}

// H = silu(G) * U  -> fp16 Hh
__global__ void k_silumul()
{
    size_t i4 = ((size_t)blockIdx.x*blockDim.x + threadIdx.x) * 4;
    size_t n = (size_t)g_totalrows * HIDn;
    if (i4 >= n) return;
    float4 g = *(float4*)&g_GBUF[i4];
    float4 u = *(float4*)&g_UBUF[i4];
    float a = (g.x / (1.f + __expf(-g.x))) * u.x;
    float b = (g.y / (1.f + __expf(-g.y))) * u.y;
    float c = (g.z / (1.f + __expf(-g.z))) * u.z;
    float d = (g.w / (1.f + __expf(-g.w))) * u.w;
    __half2 h0 = __floats2half2_rn(a, b);
    __half2 h1 = __floats2half2_rn(c, d);
    uint2 o;
    o.x = *reinterpret_cast<uint32_t*>(&h0);
    o.y = *reinterpret_cast<uint32_t*>(&h1);
    *(uint2*)&g_Hh[i4] = o;
}

// ---------------------------------------------------------------------------
extern "C" void kernel_launch(void* const* d_in, const int* in_sizes, int n_in,
                              void* d_out, int out_size)
{
    (void)in_sizes; (void)n_in;
    const float* x   = (const float*)d_in[0];
    const float* wq  = (const float*)d_in[1];
    const float* wk  = (const float*)d_in[2];
    const float* wv  = (const float*)d_in[3];
    const float* wo  = (const float*)d_in[4];
    const float* anw = (const float*)d_in[5];
    const float* fnw = (const float*)d_in[6];
    const float* gw  = (const float*)d_in[7];
    const float* wge = (const float*)d_in[8];
    const float* wue = (const float*)d_in[9];
    const float* wde = (const float*)d_in[10];
    float* out = (float*)d_out;

    float *pQ,*pK,*pV,*pH,*pXN2,*pG,*pU;
    __half *pXNh,*pATTh,*pXN2h,*pHh,*pWqh,*pWkh,*pWvh,*pWoh,*pWgeh,*pWueh,*pWdeh;
    cudaGetSymbolAddress((void**)&pQ,    g_Qb);
    cudaGetSymbolAddress((void**)&pK,    g_Kb);
    cudaGetSymbolAddress((void**)&pV,    g_Vb);
    cudaGetSymbolAddress((void**)&pH,    g_Hb);
    cudaGetSymbolAddress((void**)&pXN2,  g_XN2);
    cudaGetSymbolAddress((void**)&pG,    g_GBUF);
    cudaGetSymbolAddress((void**)&pU,    g_UBUF);
    cudaGetSymbolAddress((void**)&pXNh,  g_XNh);
    cudaGetSymbolAddress((void**)&pATTh, g_ATTh);
    cudaGetSymbolAddress((void**)&pXN2h, g_XN2h);
    cudaGetSymbolAddress((void**)&pHh,   g_Hh);
    cudaGetSymbolAddress((void**)&pWqh,  g_Wqh);
    cudaGetSymbolAddress((void**)&pWkh,  g_Wkh);
    cudaGetSymbolAddress((void**)&pWvh,  g_Wvh);
    cudaGetSymbolAddress((void**)&pWoh,  g_Woh);
    cudaGetSymbolAddress((void**)&pWgeh, g_Wgeh);
    cudaGetSymbolAddress((void**)&pWueh, g_Wueh);
    cudaGetSymbolAddress((void**)&pWdeh, g_Wdeh);

    cudaFuncSetAttribute(k_gemm<16,EPI_PLAIN,false,false>,
                         cudaFuncAttributeMaxDynamicSharedMemorySize, GEMM_SMEM);
    cudaFuncSetAttribute(k_gemm<16,EPI_RESID,false,false>,
                         cudaFuncAttributeMaxDynamicSharedMemorySize, GEMM_SMEM);
    cudaFuncSetAttribute(k_gemm<16,EPI_PLAIN,true,true>,
                         cudaFuncAttributeMaxDynamicSharedMemorySize, GEMM_SMEM);
    cudaFuncSetAttribute(k_gemm<64,EPI_DOWN,false,true>,
                         cudaFuncAttributeMaxDynamicSharedMemorySize, GEMM_SMEM);

    k_reset<<<1, 32>>>();

    // weight conversion fp32 -> fp16 (grid-stride, high ILP)
    {
        int n4 = Dn*Dn/4, blk = 256;
        k_f2h<<<512, blk>>>((const float4*)wq, (uint2*)pWqh, n4);
        k_f2h<<<512, blk>>>((const float4*)wk, (uint2*)pWkh, n4);
        k_f2h<<<512, blk>>>((const float4*)wv, (uint2*)pWvh, n4);
        k_f2h<<<512, blk>>>((const float4*)wo, (uint2*)pWoh, n4);
        int ne4 = En*HIDn*(Dn/4);
        k_f2h<<<4096, blk>>>((const float4*)wge, (uint2*)pWgeh, ne4);
        k_f2h<<<4096, blk>>>((const float4*)wue, (uint2*)pWueh, ne4);
        k_f2h<<<4096, blk>>>((const float4*)wde, (uint2*)pWdeh, ne4);
    }

    // attn pre-norm (fp16 only)
    k_rmsnorm<<<Tn, 256>>>(x, anw, nullptr, pXNh);

    // QKV projections (one launch, z selects weight/output)
    k_gemm<16,EPI_PLAIN,false,false><<<dim3(8,16,3), 256, GEMM_SMEM>>>(
        pXNh, Dn, pWqh, pWkh, pWvh, 0, Dn, pQ, pK, pV, Dn, nullptr, nullptr);

    // RoPE (Q and K in one launch)
    int nrope = Tn*NHn*32;
    k_rope<<<dim3(nrope/256, 2), 256>>>(pQ, pK);

    // attention (fp32 compute, fp16 output)
    k_attn<<<dim3(Bn*NHn, Sn/64), 256>>>(pQ, pK, pV, pATTh);

    // out proj + residual (writes H and d_out)
    k_gemm<16,EPI_RESID,false,false><<<dim3(8,16,1), 256, GEMM_SMEM>>>(
        pATTh, Dn, pWoh, pWoh, pWoh, 0, Dn, pH, pH, pH, Dn, x, out);

    // ffn pre-norm (fp32 for gating + fp16 for GEMMs)
    k_rmsnorm<<<Tn, 256>>>(pH, fnw, pXN2, pXN2h);

    // gating + routing
    k_gate<<<Tn, 256>>>(pXN2, gw);
    int write_aux = (out_size > Tn*Dn) ? 1 : 0;
    k_offsets<<<1, 256>>>(out, write_aux);
    k_scatter<<<(Tn+255)/256, 256>>>();

    // expert gate/up GEMMs (gathered rows; z selects gate vs up)
    k_gemm<16,EPI_PLAIN,true,true><<<dim3(32, MAXROWS/128, 2), 256, GEMM_SMEM>>>(
        pXN2h, Dn, pWgeh, pWueh, pWueh, (long)HIDn*Dn, Dn, pG, pU, pU, HIDn,
        nullptr, nullptr);

    // SwiGLU elementwise -> fp16
    k_silumul<<<(MAXROWS*(HIDn/4))/256, 256>>>();

    // down GEMM + gated scatter-add into out
    k_gemm<64,EPI_DOWN,false,true><<<dim3(8, MAXROWS/128, 1), 256, GEMM_SMEM>>>(
        pHh, HIDn, pWdeh, pWdeh, pWdeh, (long)Dn*HIDn, HIDn, out, out, out, Dn,
        nullptr, nullptr);
}

// round 7
// speedup vs baseline: 1.4768x; 1.4768x over previous
#include <cuda_runtime.h>
#include <cuda_fp16.h>
#include <math.h>
#include <stdint.h>

// Problem constants
#define Bn 2
#define Sn 1024
#define Dn 1024
#define NHn 16
#define HDn 64
#define En 8
#define HIDn 4096
#define Tn (Bn*Sn)          // 2048 tokens
#define MAXROWS 5248        // >= 4096 assignments + 8*127 padding, mult of 128

// ---------------- scratch (static device globals; no allocation) -------------
static __device__ __half g_XNh [Tn*Dn];
static __device__ float  g_Qb  [Tn*Dn];
static __device__ float  g_Kb  [Tn*Dn];
static __device__ float  g_Vb  [Tn*Dn];
static __device__ __half g_ATTh[Tn*Dn];
static __device__ float  g_Hb  [Tn*Dn];
static __device__ float  g_XN2 [Tn*Dn];
static __device__ __half g_XN2h[Tn*Dn];
static __device__ float  g_GBUF[(size_t)MAXROWS*HIDn];
static __device__ float  g_UBUF[(size_t)MAXROWS*HIDn];
static __device__ __half g_Hh  [(size_t)MAXROWS*HIDn];
// fp16 weights
static __device__ __half g_Wqh[Dn*Dn];
static __device__ __half g_Wkh[Dn*Dn];
static __device__ __half g_Wvh[Dn*Dn];
static __device__ __half g_Woh[Dn*Dn];
static __device__ __half g_Wgeh[(size_t)En*HIDn*Dn];
static __device__ __half g_Wueh[(size_t)En*HIDn*Dn];
static __device__ __half g_Wdeh[(size_t)En*Dn*HIDn];
// routing
static __device__ int   g_cnt[En];
static __device__ int   g_cursor[En];
static __device__ int   g_rowtok[MAXROWS];
static __device__ int   g_rowexp[MAXROWS];
static __device__ float g_rowgate[MAXROWS];
static __device__ int   g_totalrows;
static __device__ float g_gsum[En];
static __device__ float g_psum[En];
static __device__ int   g_expid[Tn*2];
static __device__ float g_gateval[Tn*2];

// ======================= PTX helpers =========================================
static __device__ __forceinline__ uint32_t smem_u32_(const void* p){
    uint32_t a;
    asm("{ .reg .u64 t; cvta.to.shared.u64 t, %1; cvt.u32.u64 %0, t; }"
        : "=r"(a) : "l"(p));
    return a;
}

#define LDSM_X4(r0,r1,r2,r3,addr) \
    asm volatile("ldmatrix.sync.aligned.m8n8.x4.shared.b16 {%0,%1,%2,%3}, [%4];" \
        : "=r"(r0),"=r"(r1),"=r"(r2),"=r"(r3) : "r"(addr))

#define MMA16816(c,a,b) \
    asm volatile("mma.sync.aligned.m16n8k16.row.col.f32.f16.f16.f32 " \
        "{%0,%1,%2,%3}, {%4,%5,%6,%7}, {%8,%9}, {%0,%1,%2,%3};" \
        : "+f"((c)[0]),"+f"((c)[1]),"+f"((c)[2]),"+f"((c)[3]) \
        : "r"((a)[0]),"r"((a)[1]),"r"((a)[2]),"r"((a)[3]), \
          "r"((b)[0]),"r"((b)[1]))

#define CP_COMMIT() asm volatile("cp.async.commit_group;" ::: "memory")
#define CP_WAIT(N)  asm volatile("cp.async.wait_group %0;" :: "n"(N) : "memory")

static __device__ __forceinline__ void cp16_(uint32_t dst, const void* src, int srcsize){
    asm volatile("cp.async.cg.shared.global [%0], [%1], 16, %2;"
        :: "r"(dst), "l"((unsigned long long)__cvta_generic_to_global(src)),
           "r"(srcsize) : "memory");
}

// ============================== small kernels ================================
__global__ void k_reset() {
    int i = threadIdx.x;
    if (i < En) { g_cnt[i] = 0; g_gsum[i] = 0.f; g_psum[i] = 0.f; }
}

// fp32 -> fp16 conversion, 4 elems/thread (one float4), big grid
__global__ void k_f2h(const float4* __restrict__ s, uint2* __restrict__ d, int n4){
    int i = blockIdx.x*blockDim.x + threadIdx.x;
    if (i >= n4) return;
    float4 v = s[i];
    __half2 h0 = __floats2half2_rn(v.x, v.y);
    __half2 h1 = __floats2half2_rn(v.z, v.w);
    uint2 o;
    o.x = *reinterpret_cast<uint32_t*>(&h0);
    o.y = *reinterpret_cast<uint32_t*>(&h1);
    d[i] = o;
}

__global__ void k_rmsnorm(const float* __restrict__ x, const float* __restrict__ w,
                          float* __restrict__ y, __half* __restrict__ yh) {
    int t = blockIdx.x;
    const float* xr = x + (size_t)t * Dn;
    int base = threadIdx.x * 4;
    float4 xv = *(const float4*)(xr + base);
    float ss = xv.x*xv.x + xv.y*xv.y + xv.z*xv.z + xv.w*xv.w;
    #pragma unroll
    for (int o = 16; o; o >>= 1) ss += __shfl_xor_sync(0xffffffffu, ss, o);
    __shared__ float ws[8];
    if ((threadIdx.x & 31) == 0) ws[threadIdx.x >> 5] = ss;
    __syncthreads();
    float tot = ws[0]+ws[1]+ws[2]+ws[3]+ws[4]+ws[5]+ws[6]+ws[7];
    float sc = rsqrtf(tot * (1.f/(float)Dn) + 1e-6f);
    float4 wv = *(const float4*)(w + base);
    float4 o4;
    o4.x = wv.x*xv.x*sc; o4.y = wv.y*xv.y*sc;
    o4.z = wv.z*xv.z*sc; o4.w = wv.w*xv.w*sc;
    if (y) *(float4*)(y + (size_t)t*Dn + base) = o4;
    __half2 h0 = __floats2half2_rn(o4.x, o4.y);
    __half2 h1 = __floats2half2_rn(o4.z, o4.w);
    uint2 ho;
    ho.x = *reinterpret_cast<uint32_t*>(&h0);
    ho.y = *reinterpret_cast<uint32_t*>(&h1);
    *(uint2*)(yh + (size_t)t*Dn + base) = ho;
}

// ===================== mma.sync GEMM (HMMA tensor path) ======================
// Exact Round-4 (858us) structure: 128x128x64 tile, 3-stage cp.async, 8 warps.
#define EPI_PLAIN 0
#define EPI_RESID 1
#define EPI_DOWN  2
#define GEMM_SMEM (3*32768)

template<int NITER, int EPI, bool GATHER, bool ESEL>
__global__ __launch_bounds__(256)
void k_gemm(const __half* __restrict__ A0, int lda,
            const __half* __restrict__ B0, const __half* __restrict__ B1,
            const __half* __restrict__ B2,
            long bstride, int ldb,
            float* __restrict__ C0, float* __restrict__ C1c, float* __restrict__ C2c,
            int ldc,
            const float* __restrict__ resid, float* __restrict__ Cdual)
{
    constexpr int S = 3;
    int mt = blockIdx.y, nt = blockIdx.x;
    if (ESEL && mt*128 >= g_totalrows) return;
    const __half* Bh = (blockIdx.z==0) ? B0 : ((blockIdx.z==1) ? B1 : B2);
    float* C = (blockIdx.z==0) ? C0 : ((blockIdx.z==1) ? C1c : C2c);
    if (ESEL) Bh += (long)g_rowexp[mt*128] * bstride;

    extern __shared__ __align__(128) char sm_[];
    uint32_t sbase = smem_u32_(sm_);

    int tid = threadIdx.x, lane = tid & 31, wid = tid >> 5;
    int warp_m = wid & 3, warp_n = wid >> 2;

    int lrow = tid >> 1;
    int lc0  = (tid & 1) * 4;
    const __half* asrc;
    bool avalid = true;
    if (GATHER){
        int tok = g_rowtok[mt*128 + lrow];
        avalid = (tok >= 0);
        asrc = A0 + (avalid ? (size_t)tok * lda : 0);
    } else {
        asrc = A0 + (size_t)(mt*128 + lrow) * lda;
    }
    const __half* bsrc = Bh + (size_t)(nt*128 + lrow) * ldb;
    int asz = avalid ? 16 : 0;
    uint32_t arow_s = sbase + lrow*128;
    uint32_t brow_s = arow_s + 16384;

    auto stg = [&](int it){
        int stage = it % S;
        uint32_t so = (uint32_t)stage * 32768u;
        const char* ag = (const char*)(asrc + it*64);
        const char* bg = (const char*)(bsrc + it*64);
        #pragma unroll
        for (int i = 0; i < 4; i++){
            int c = lc0 + i;
            uint32_t sw = (uint32_t)((c ^ (lrow & 7)) * 16);
            cp16_(arow_s + so + sw, ag + c*16, asz);
            cp16_(brow_s + so + sw, bg + c*16, 16);
        }
    };

    float acc[2][8][4];
    #pragma unroll
    for (int i=0;i<2;i++)
        #pragma unroll
        for (int j=0;j<8;j++)
            #pragma unroll
            for (int k=0;k<4;k++) acc[i][j][k]=0.f;

    #pragma unroll
    for (int it = 0; it < S-1; it++){ stg(it); CP_COMMIT(); }

    int a_rlo = (lane & 15);
    int a_chk = (lane >> 4);
    int b_rlo = (lane & 7) + ((lane & 16) ? 8 : 0);
    int b_chk = (lane >> 3) & 1;

    for (int it = 0; it < NITER; it++){
        CP_WAIT(S-2);
        __syncthreads();
        if (it + S-1 < NITER) stg(it + S-1);
        CP_COMMIT();

        uint32_t so = (uint32_t)(it % S) * 32768u;
        uint32_t abase = sbase + so;
        uint32_t bbase = abase + 16384;

        #pragma unroll
        for (int ks = 0; ks < 4; ks++){
            uint32_t a[2][4];
            #pragma unroll
            for (int mtile = 0; mtile < 2; mtile++){
                int row = warp_m*32 + mtile*16 + a_rlo;
                int chunk = 2*ks + a_chk;
                uint32_t addr = abase + row*128 + ((chunk ^ (row & 7)) * 16);
                LDSM_X4(a[mtile][0], a[mtile][1], a[mtile][2], a[mtile][3], addr);
            }
            uint32_t b[8][2];
            #pragma unroll
            for (int n2 = 0; n2 < 4; n2++){
                int row = warp_n*64 + n2*16 + b_rlo;
                int chunk = 2*ks + b_chk;
                uint32_t addr = bbase + row*128 + ((chunk ^ (row & 7)) * 16);
                uint32_t r0,r1,r2,r3;
                LDSM_X4(r0, r1, r2, r3, addr);
                b[2*n2][0]=r0; b[2*n2][1]=r1;
                b[2*n2+1][0]=r2; b[2*n2+1][1]=r3;
            }
            #pragma unroll
            for (int mtile = 0; mtile < 2; mtile++)
                #pragma unroll
                for (int n8 = 0; n8 < 8; n8++)
                    MMA16816(acc[mtile][n8], a[mtile], b[n8]);
        }
        __syncthreads();
    }

    // ---- epilogue ----
    int m0 = mt*128 + warp_m*32;
    int n0 = nt*128 + warp_n*64;
    int gq = lane >> 2, tq = lane & 3;
    #pragma unroll
    for (int mtile = 0; mtile < 2; mtile++){
        int r_lo = m0 + mtile*16 + gq;
        int r_hi = r_lo + 8;
        if (EPI == EPI_DOWN){
            int tok_lo = g_rowtok[r_lo], tok_hi = g_rowtok[r_hi];
            float gl = g_rowgate[r_lo], gh = g_rowgate[r_hi];
            #pragma unroll
            for (int n8 = 0; n8 < 8; n8++){
                int col = n0 + n8*8 + tq*2;
                if (tok_lo >= 0){
                    size_t o = (size_t)tok_lo*ldc + col;
                    atomicAdd(&C[o],   gl*acc[mtile][n8][0]);
                    atomicAdd(&C[o+1], gl*acc[mtile][n8][1]);
                }
                if (tok_hi >= 0){
                    size_t o = (size_t)tok_hi*ldc + col;
                    atomicAdd(&C[o],   gh*acc[mtile][n8][2]);
                    atomicAdd(&C[o+1], gh*acc[mtile][n8][3]);
                }
            }
        } else if (EPI == EPI_RESID){
            #pragma unroll
            for (int n8 = 0; n8 < 8; n8++){
                int col = n0 + n8*8 + tq*2;
                size_t o_lo = (size_t)r_lo*ldc + col;
                size_t o_hi = (size_t)r_hi*ldc + col;
                float2 rv0 = *(const float2*)(resid + o_lo);
                float2 rv1 = *(const float2*)(resid + o_hi);
                float2 v0, v1;
                v0.x = acc[mtile][n8][0] + rv0.x;
                v0.y = acc[mtile][n8][1] + rv0.y;
                v1.x = acc[mtile][n8][2] + rv1.x;
                v1.y = acc[mtile][n8][3] + rv1.y;
                *(float2*)(C + o_lo) = v0;
                *(float2*)(C + o_hi) = v1;
                *(float2*)(Cdual + o_lo) = v0;
                *(float2*)(Cdual + o_hi) = v1;
            }
        } else {
            #pragma unroll
            for (int n8 = 0; n8 < 8; n8++){
                int col = n0 + n8*8 + tq*2;
                float2 v0, v1;
                v0.x = acc[mtile][n8][0]; v0.y = acc[mtile][n8][1];
                v1.x = acc[mtile][n8][2]; v1.y = acc[mtile][n8][3];
                *(float2*)(C + (size_t)r_lo*ldc + col) = v0;
                *(float2*)(C + (size_t)r_hi*ldc + col) = v1;
            }
        }
    }
}

// ============================ RoPE / attention ===============================
// blockIdx.y==0 -> Q, ==1 -> K
__global__ void k_rope(float* __restrict__ q, float* __restrict__ kk) {
    int idx = blockIdx.x*blockDim.x + threadIdx.x;
    if (idx >= Tn*NHn*32) return;
    float* dst = blockIdx.y ? kk : q;
    int i = idx & 31;
    int t = idx >> 9;
    int h = (idx >> 5) & (NHn-1);
    int s = t & (Sn-1);
    float invf = powf(10000.f, -((float)(2*i)) * (1.f/(float)HDn));
    float fr = (float)s * invf;
    float c, sn;
    sincosf(fr, &sn, &c);
    float* p = dst + (size_t)t*Dn + h*HDn + i;
    float v1 = p[0], v2 = p[32];
    p[0]  = v1*c - v2*sn;
    p[32] = v2*c + v1*sn;
}

__global__ __launch_bounds__(256)
void k_attn(const float* __restrict__ Q, const float* __restrict__ Kg,
            const float* __restrict__ V, __half* __restrict__ O)
{
    __shared__ float Qs [64*64];
    __shared__ float KVs[64*64];
    __shared__ float Ps [64*64];
    int bh = blockIdx.x;
    int qt = blockIdx.y;
    int b = bh >> 4, h = bh & 15;
    int tid = threadIdx.x;
    int ty = tid >> 4, tx = tid & 15;
    size_t base = ((size_t)b*Sn)*Dn + (size_t)h*HDn;
    int q0 = qt*64;
    #pragma unroll
    for (int rep=0;rep<4;rep++){
        int lin = tid + rep*256;
        int r = lin >> 4, c = (lin & 15)*4;
        *(float4*)&Qs[r*64+c] = *(const float4*)(Q + base + (size_t)(q0+r)*Dn + c);
    }
    float acc[4][4];
    float mrow[4], lrow[4];
    #pragma unroll
    for (int i=0;i<4;i++){
        mrow[i] = -1e30f; lrow[i] = 0.f;
        #pragma unroll
        for (int j=0;j<4;j++) acc[i][j]=0.f;
    }
    __syncthreads();
    for (int kt=0; kt<=qt; kt++){
        int k0 = kt*64;
        #pragma unroll
        for (int rep=0;rep<4;rep++){
            int lin = tid + rep*256;
            int r = lin >> 4, c = (lin & 15)*4;
            float4 kv = *(const float4*)(Kg + base + (size_t)(k0+r)*Dn + c);
            KVs[(c+0)*64 + r] = kv.x;
            KVs[(c+1)*64 + r] = kv.y;
            KVs[(c+2)*64 + r] = kv.z;
            KVs[(c+3)*64 + r] = kv.w;
        }
        __syncthreads();
        float s[4][4];
        #pragma unroll
        for (int i=0;i<4;i++)
            #pragma unroll
            for (int j=0;j<4;j++) s[i][j]=0.f;
        #pragma unroll 4
        for (int d=0; d<64; d++){
            float qa[4], kb[4];
            #pragma unroll
            for (int i=0;i<4;i++) qa[i] = Qs[(ty*4+i)*64 + d];
            #pragma unroll
            for (int j=0;j<4;j++) kb[j] = KVs[d*64 + tx*4 + j];
            #pragma unroll
            for (int i=0;i<4;i++)
                #pragma unroll
                for (int j=0;j<4;j++) s[i][j] = fmaf(qa[i], kb[j], s[i][j]);
        }
        #pragma unroll
        for (int i=0;i<4;i++){
            int qq = q0 + ty*4 + i;
            #pragma unroll
            for (int j=0;j<4;j++){
                int kk = k0 + tx*4 + j;
                s[i][j] = (kk <= qq) ? s[i][j]*0.125f : -1e30f;
            }
        }
        #pragma unroll
        for (int i=0;i<4;i++){
            float mt = fmaxf(fmaxf(s[i][0],s[i][1]), fmaxf(s[i][2],s[i][3]));
            #pragma unroll
            for (int o=8;o;o>>=1) mt = fmaxf(mt, __shfl_xor_sync(0xffffffffu, mt, o));
            float mn = fmaxf(mrow[i], mt);
            float corr = __expf(mrow[i] - mn);
            float rs = 0.f;
            #pragma unroll
            for (int j=0;j<4;j++){ float p = __expf(s[i][j]-mn); s[i][j]=p; rs+=p; }
            #pragma unroll
            for (int o=8;o;o>>=1) rs += __shfl_xor_sync(0xffffffffu, rs, o);
            lrow[i] = lrow[i]*corr + rs;
            mrow[i] = mn;
            #pragma unroll
            for (int j=0;j<4;j++) acc[i][j] *= corr;
            #pragma unroll
            for (int j=0;j<4;j++) Ps[(ty*4+i)*64 + tx*4+j] = s[i][j];
        }
        __syncthreads();
        #pragma unroll
        for (int rep=0;rep<4;rep++){
            int lin = tid + rep*256;
            int r = lin >> 4, c = (lin & 15)*4;
            *(float4*)&KVs[r*64+c] = *(const float4*)(V + base + (size_t)(k0+r)*Dn + c);
        }
        __syncthreads();
        #pragma unroll 4
        for (int kv=0; kv<64; kv++){
            float pv[4], vv[4];
            #pragma unroll
            for (int i=0;i<4;i++) pv[i] = Ps[(ty*4+i)*64 + kv];
            #pragma unroll
            for (int j=0;j<4;j++) vv[j] = KVs[kv*64 + tx*4 + j];
            #pragma unroll
            for (int i=0;i<4;i++)
                #pragma unroll
                for (int j=0;j<4;j++) acc[i][j] = fmaf(pv[i], vv[j], acc[i][j]);
        }
        __syncthreads();
    }
    #pragma unroll
    for (int i=0;i<4;i++){
        float inv = 1.f/lrow[i];
        size_t o = base + (size_t)(q0+ty*4+i)*Dn + tx*4;
        __half2 p0 = __floats2half2_rn(acc[i][0]*inv, acc[i][1]*inv);
        __half2 p1 = __floats2half2_rn(acc[i][2]*inv, acc[i][3]*inv);
        *(__half2*)(O + o)     = p0;
        *(__half2*)(O + o + 2) = p1;
    }
}

// =============================== gating / MoE ================================
__global__ void k_gate(const float* __restrict__ xn, const float* __restrict__ gw)
{
    int t = blockIdx.x;
    int w = threadIdx.x >> 5, lane = threadIdx.x & 31;
    const float* xr = xn + (size_t)t * Dn;
    const float* gr = gw + (size_t)w * Dn;
    float acc = 0.f;
    for (int d = lane; d < Dn; d += 32) acc = fmaf(xr[d], gr[d], acc);
    #pragma unroll
    for (int o=16;o;o>>=1) acc += __shfl_xor_sync(0xffffffffu, acc, o);
    __shared__ float lg[En];
    if (lane == 0) lg[w] = acc;
    __syncthreads();
    if (threadIdx.x == 0){
        int i1 = 0;
        for (int e=1;e<En;e++) if (lg[e] > lg[i1]) i1 = e;
        int i2 = -1;
        for (int e=0;e<En;e++){
            if (e == i1) continue;
            if (i2 < 0 || lg[e] > lg[i2]) i2 = e;
        }
        float l1 = lg[i1], l2 = lg[i2];
        float e2 = expf(l2 - l1);
        float inv = 1.f/(1.f + e2);
        float gv1 = inv, gv2 = e2*inv;
        g_expid[t*2]   = i1; g_expid[t*2+1]   = i2;
        g_gateval[t*2] = gv1; g_gateval[t*2+1] = gv2;
        atomicAdd(&g_cnt[i1], 1); atomicAdd(&g_cnt[i2], 1);
        atomicAdd(&g_gsum[i1], gv1); atomicAdd(&g_gsum[i2], gv2);
        float mx = lg[0];
        for (int e=1;e<En;e++) mx = fmaxf(mx, lg[e]);
        float pe[En]; float se = 0.f;
        for (int e=0;e<En;e++){ pe[e] = expf(lg[e]-mx); se += pe[e]; }
        float pinv = 1.f/se;
        for (int e=0;e<En;e++) atomicAdd(&g_psum[e], pe[e]*pinv);
    }
}

__global__ void k_offsets(float* __restrict__ out, int write_aux)
{
    __shared__ int soff[En+1];
    if (threadIdx.x == 0){
        int tot = 0;
        for (int e=0;e<En;e++){
            soff[e] = tot;
            g_cursor[e] = tot;
            tot += ((g_cnt[e] + 127) >> 7) << 7;
        }
        soff[En] = tot;
        g_totalrows = tot;
        if (write_aux){
            float sacc = 0.f;
            for (int e=0;e<En;e++) sacc += g_gsum[e]*g_psum[e];
            out[(size_t)Tn*Dn] = (float)En * sacc / ((float)Tn*(float)Tn);
        }
    }
    __syncthreads();
    int tot = soff[En];
    for (int r = threadIdx.x; r < tot; r += blockDim.x){
        int e = 0;
        while (e+1 < En && r >= soff[e+1]) e++;
        g_rowexp[r] = e;
        g_rowtok[r] = -1;
    }
}

__global__ void k_scatter()
{
    int t = blockIdx.x*blockDim.x + threadIdx.x;
    if (t >= Tn) return;
    #pragma unroll
    for (int k=0;k<2;k++){
        int e = g_expid[t*2+k];
        int pos = atomicAdd(&g_cursor[e], 1);
        g_rowtok[pos] = t;
        g_rowgate[pos] = g_gateval[t*2+k];
    }
}

// H = silu(G) * U  -> fp16 Hh
__global__ void k_silumul()
{
    size_t i4 = ((size_t)blockIdx.x*blockDim.x + threadIdx.x) * 4;
    size_t n = (size_t)g_totalrows * HIDn;
    if (i4 >= n) return;
    float4 g = *(float4*)&g_GBUF[i4];
    float4 u = *(float4*)&g_UBUF[i4];
    float a = (g.x / (1.f + __expf(-g.x))) * u.x;
    float b = (g.y / (1.f + __expf(-g.y))) * u.y;
    float c = (g.z / (1.f + __expf(-g.z))) * u.z;
    float d = (g.w / (1.f + __expf(-g.w))) * u.w;
    __half2 h0 = __floats2half2_rn(a, b);
    __half2 h1 = __floats2half2_rn(c, d);
    uint2 o;
    o.x = *reinterpret_cast<uint32_t*>(&h0);
    o.y = *reinterpret_cast<uint32_t*>(&h1);
    *(uint2*)&g_Hh[i4] = o;
}

// ---------------------------------------------------------------------------
extern "C" void kernel_launch(void* const* d_in, const int* in_sizes, int n_in,
                              void* d_out, int out_size)
{
    (void)in_sizes; (void)n_in;
    const float* x   = (const float*)d_in[0];
    const float* wq  = (const float*)d_in[1];
    const float* wk  = (const float*)d_in[2];
    const float* wv  = (const float*)d_in[3];
    const float* wo  = (const float*)d_in[4];
    const float* anw = (const float*)d_in[5];
    const float* fnw = (const float*)d_in[6];
    const float* gw  = (const float*)d_in[7];
    const float* wge = (const float*)d_in[8];
    const float* wue = (const float*)d_in[9];
    const float* wde = (const float*)d_in[10];
    float* out = (float*)d_out;

    float *pQ,*pK,*pV,*pH,*pXN2,*pG,*pU;
    __half *pXNh,*pATTh,*pXN2h,*pHh,*pWqh,*pWkh,*pWvh,*pWoh,*pWgeh,*pWueh,*pWdeh;
    cudaGetSymbolAddress((void**)&pQ,    g_Qb);
    cudaGetSymbolAddress((void**)&pK,    g_Kb);
    cudaGetSymbolAddress((void**)&pV,    g_Vb);
    cudaGetSymbolAddress((void**)&pH,    g_Hb);
    cudaGetSymbolAddress((void**)&pXN2,  g_XN2);
    cudaGetSymbolAddress((void**)&pG,    g_GBUF);
    cudaGetSymbolAddress((void**)&pU,    g_UBUF);
    cudaGetSymbolAddress((void**)&pXNh,  g_XNh);
    cudaGetSymbolAddress((void**)&pATTh, g_ATTh);
    cudaGetSymbolAddress((void**)&pXN2h, g_XN2h);
    cudaGetSymbolAddress((void**)&pHh,   g_Hh);
    cudaGetSymbolAddress((void**)&pWqh,  g_Wqh);
    cudaGetSymbolAddress((void**)&pWkh,  g_Wkh);
    cudaGetSymbolAddress((void**)&pWvh,  g_Wvh);
    cudaGetSymbolAddress((void**)&pWoh,  g_Woh);
    cudaGetSymbolAddress((void**)&pWgeh, g_Wgeh);
    cudaGetSymbolAddress((void**)&pWueh, g_Wueh);
    cudaGetSymbolAddress((void**)&pWdeh, g_Wdeh);

    cudaFuncSetAttribute(k_gemm<16,EPI_PLAIN,false,false>,
                         cudaFuncAttributeMaxDynamicSharedMemorySize, GEMM_SMEM);
    cudaFuncSetAttribute(k_gemm<16,EPI_RESID,false,false>,
                         cudaFuncAttributeMaxDynamicSharedMemorySize, GEMM_SMEM);
    cudaFuncSetAttribute(k_gemm<16,EPI_PLAIN,true,true>,
                         cudaFuncAttributeMaxDynamicSharedMemorySize, GEMM_SMEM);
    cudaFuncSetAttribute(k_gemm<64,EPI_DOWN,false,true>,
                         cudaFuncAttributeMaxDynamicSharedMemorySize, GEMM_SMEM);

    // side stream for expert-weight conversion, overlapped with attention path
    static cudaStream_t s2 = nullptr;
    static cudaEvent_t evFork = nullptr, evJoin = nullptr;
    if (!s2){
        cudaStreamCreateWithFlags(&s2, cudaStreamNonBlocking);
        cudaEventCreateWithFlags(&evFork, cudaEventDisableTiming);
        cudaEventCreateWithFlags(&evJoin, cudaEventDisableTiming);
    }

    k_reset<<<1, 32>>>();

    // ---- fork: expert weight conversions on s2 (no deps on main path) ----
    cudaEventRecord(evFork, 0);
    cudaStreamWaitEvent(s2, evFork, 0);
    {
        int ne4 = En*HIDn*(Dn/4), blk = 256, g2 = (ne4+blk-1)/blk;
        k_f2h<<<g2, blk, 0, s2>>>((const float4*)wge, (uint2*)pWgeh, ne4);
        k_f2h<<<g2, blk, 0, s2>>>((const float4*)wue, (uint2*)pWueh, ne4);
        k_f2h<<<g2, blk, 0, s2>>>((const float4*)wde, (uint2*)pWdeh, ne4);
    }
    cudaEventRecord(evJoin, s2);

    // ---- main stream: attention path ----
    {
        int n4 = Dn*Dn/4, blk = 256, g1 = (n4+blk-1)/blk;
        k_f2h<<<g1, blk>>>((const float4*)wq, (uint2*)pWqh, n4);
        k_f2h<<<g1, blk>>>((const float4*)wk, (uint2*)pWkh, n4);
        k_f2h<<<g1, blk>>>((const float4*)wv, (uint2*)pWvh, n4);
        k_f2h<<<g1, blk>>>((const float4*)wo, (uint2*)pWoh, n4);
    }

    k_rmsnorm<<<Tn, 256>>>(x, anw, nullptr, pXNh);

    k_gemm<16,EPI_PLAIN,false,false><<<dim3(8,16,3), 256, GEMM_SMEM>>>(
        pXNh, Dn, pWqh, pWkh, pWvh, 0, Dn, pQ, pK, pV, Dn, nullptr, nullptr);

    int nrope = Tn*NHn*32;
    k_rope<<<dim3(nrope/256, 2), 256>>>(pQ, pK);

    k_attn<<<dim3(Bn*NHn, Sn/64), 256>>>(pQ, pK, pV, pATTh);

    k_gemm<16,EPI_RESID,false,false><<<dim3(8,16,1), 256, GEMM_SMEM>>>(
        pATTh, Dn, pWoh, pWoh, pWoh, 0, Dn, pH, pH, pH, Dn, x, out);

    k_rmsnorm<<<Tn, 256>>>(pH, fnw, pXN2, pXN2h);

    k_gate<<<Tn, 256>>>(pXN2, gw);
    int write_aux = (out_size > Tn*Dn) ? 1 : 0;
    k_offsets<<<1, 256>>>(out, write_aux);
    k_scatter<<<(Tn+255)/256, 256>>>();

    // ---- join: expert GEMMs need the converted weights ----
    cudaStreamWaitEvent(0, evJoin, 0);

    k_gemm<16,EPI_PLAIN,true,true><<<dim3(32, MAXROWS/128, 2), 256, GEMM_SMEM>>>(
        pXN2h, Dn, pWgeh, pWueh, pWueh, (long)HIDn*Dn, Dn, pG, pU, pU, HIDn,
        nullptr, nullptr);

    k_silumul<<<(MAXROWS*(HIDn/4))/256, 256>>>();

    k_gemm<64,EPI_DOWN,false,true><<<dim3(8, MAXROWS/128, 1), 256, GEMM_SMEM>>>(
        pHh, HIDn, pWdeh, pWdeh, pWdeh, (long)Dn*HIDn, HIDn, out, out, out, Dn,
        nullptr, nullptr);
}

// round 8
// speedup vs baseline: 1.5020x; 1.0171x over previous
#include <cuda_runtime.h>
#include <cuda_fp16.h>
#include <math.h>
#include <stdint.h>

// Problem constants
#define Bn 2
#define Sn 1024
#define Dn 1024
#define NHn 16
#define HDn 64
#define En 8
#define HIDn 4096
#define Tn (Bn*Sn)          // 2048 tokens
#define MAXROWS 5248        // >= 4096 assignments + 8*127 padding, mult of 128

// ---------------- scratch (static device globals; no allocation) -------------
static __device__ __half g_XNh [Tn*Dn];
static __device__ float  g_Qb  [Tn*Dn];
static __device__ float  g_Kb  [Tn*Dn];
static __device__ float  g_Vb  [Tn*Dn];
static __device__ __half g_ATTh[Tn*Dn];
static __device__ float  g_Hb  [Tn*Dn];
static __device__ float  g_XN2 [Tn*Dn];
static __device__ __half g_XN2h[Tn*Dn];
static __device__ __half g_GBh [(size_t)MAXROWS*HIDn];
static __device__ __half g_UBh [(size_t)MAXROWS*HIDn];
static __device__ __half g_Hh  [(size_t)MAXROWS*HIDn];
// fp16 weights
static __device__ __half g_Wqh[Dn*Dn];
static __device__ __half g_Wkh[Dn*Dn];
static __device__ __half g_Wvh[Dn*Dn];
static __device__ __half g_Woh[Dn*Dn];
static __device__ __half g_Wgeh[(size_t)En*HIDn*Dn];
static __device__ __half g_Wueh[(size_t)En*HIDn*Dn];
static __device__ __half g_Wdeh[(size_t)En*Dn*HIDn];
// routing
static __device__ int   g_cnt[En];
static __device__ int   g_cursor[En];
static __device__ int   g_rowtok[MAXROWS];
static __device__ int   g_rowexp[MAXROWS];
static __device__ float g_rowgate[MAXROWS];
static __device__ int   g_totalrows;
static __device__ float g_gsum[En];
static __device__ float g_psum[En];
static __device__ int   g_expid[Tn*2];
static __device__ float g_gateval[Tn*2];

// ======================= PTX helpers =========================================
static __device__ __forceinline__ uint32_t smem_u32_(const void* p){
    uint32_t a;
    asm("{ .reg .u64 t; cvta.to.shared.u64 t, %1; cvt.u32.u64 %0, t; }"
        : "=r"(a) : "l"(p));
    return a;
}

#define LDSM_X4(r0,r1,r2,r3,addr) \
    asm volatile("ldmatrix.sync.aligned.m8n8.x4.shared.b16 {%0,%1,%2,%3}, [%4];" \
        : "=r"(r0),"=r"(r1),"=r"(r2),"=r"(r3) : "r"(addr))

#define MMA16816(c,a,b) \
    asm volatile("mma.sync.aligned.m16n8k16.row.col.f32.f16.f16.f32 " \
        "{%0,%1,%2,%3}, {%4,%5,%6,%7}, {%8,%9}, {%0,%1,%2,%3};" \
        : "+f"((c)[0]),"+f"((c)[1]),"+f"((c)[2]),"+f"((c)[3]) \
        : "r"((a)[0]),"r"((a)[1]),"r"((a)[2]),"r"((a)[3]), \
          "r"((b)[0]),"r"((b)[1]))

#define CP_COMMIT() asm volatile("cp.async.commit_group;" ::: "memory")
#define CP_WAIT(N)  asm volatile("cp.async.wait_group %0;" :: "n"(N) : "memory")

static __device__ __forceinline__ void cp16_(uint32_t dst, const void* src, int srcsize){
    asm volatile("cp.async.cg.shared.global [%0], [%1], 16, %2;"
        :: "r"(dst), "l"((unsigned long long)__cvta_generic_to_global(src)),
           "r"(srcsize) : "memory");
}

// ============================== small kernels ================================
__global__ void k_reset() {
    int i = threadIdx.x;
    if (i < En) { g_cnt[i] = 0; g_gsum[i] = 0.f; g_psum[i] = 0.f; }
}

static __device__ __forceinline__ void f2h_one_(const float4* s, uint2* d, int i){
    float4 v = s[i];
    __half2 h0 = __floats2half2_rn(v.x, v.y);
    __half2 h1 = __floats2half2_rn(v.z, v.w);
    uint2 o;
    o.x = *reinterpret_cast<uint32_t*>(&h0);
    o.y = *reinterpret_cast<uint32_t*>(&h1);
    d[i] = o;
}

// 2-matrix fused f2h (blockIdx.y selects)
__global__ void k_f2h2(const float4* __restrict__ s0, const float4* __restrict__ s1,
                       uint2* __restrict__ d0, uint2* __restrict__ d1, int n4){
    int i = blockIdx.x*blockDim.x + threadIdx.x;
    if (i >= n4) return;
    if (blockIdx.y == 0) f2h_one_(s0, d0, i);
    else                 f2h_one_(s1, d1, i);
}

// 4-matrix fused f2h
__global__ void k_f2h4(const float4* __restrict__ s0, const float4* __restrict__ s1,
                       const float4* __restrict__ s2p, const float4* __restrict__ s3,
                       uint2* __restrict__ d0, uint2* __restrict__ d1,
                       uint2* __restrict__ d2, uint2* __restrict__ d3, int n4){
    int i = blockIdx.x*blockDim.x + threadIdx.x;
    if (i >= n4) return;
    switch (blockIdx.y){
        case 0: f2h_one_(s0, d0, i); break;
        case 1: f2h_one_(s1, d1, i); break;
        case 2: f2h_one_(s2p, d2, i); break;
        default: f2h_one_(s3, d3, i); break;
    }
}

__global__ void k_f2h(const float4* __restrict__ s, uint2* __restrict__ d, int n4){
    int i = blockIdx.x*blockDim.x + threadIdx.x;
    if (i >= n4) return;
    f2h_one_(s, d, i);
}

__global__ void k_rmsnorm(const float* __restrict__ x, const float* __restrict__ w,
                          float* __restrict__ y, __half* __restrict__ yh) {
    int t = blockIdx.x;
    const float* xr = x + (size_t)t * Dn;
    int base = threadIdx.x * 4;
    float4 xv = *(const float4*)(xr + base);
    float ss = xv.x*xv.x + xv.y*xv.y + xv.z*xv.z + xv.w*xv.w;
    #pragma unroll
    for (int o = 16; o; o >>= 1) ss += __shfl_xor_sync(0xffffffffu, ss, o);
    __shared__ float ws[8];
    if ((threadIdx.x & 31) == 0) ws[threadIdx.x >> 5] = ss;
    __syncthreads();
    float tot = ws[0]+ws[1]+ws[2]+ws[3]+ws[4]+ws[5]+ws[6]+ws[7];
    float sc = rsqrtf(tot * (1.f/(float)Dn) + 1e-6f);
    float4 wv = *(const float4*)(w + base);
    float4 o4;
    o4.x = wv.x*xv.x*sc; o4.y = wv.y*xv.y*sc;
    o4.z = wv.z*xv.z*sc; o4.w = wv.w*xv.w*sc;
    if (y) *(float4*)(y + (size_t)t*Dn + base) = o4;
    __half2 h0 = __floats2half2_rn(o4.x, o4.y);
    __half2 h1 = __floats2half2_rn(o4.z, o4.w);
    uint2 ho;
    ho.x = *reinterpret_cast<uint32_t*>(&h0);
    ho.y = *reinterpret_cast<uint32_t*>(&h1);
    *(uint2*)(yh + (size_t)t*Dn + base) = ho;
}

// ===================== mma.sync GEMM (HMMA tensor path) ======================
// Measured-best Round-4 structure: 128x128x64 tile, 3-stage cp.async, 8 warps.
#define EPI_PLAIN 0
#define EPI_RESID 1
#define EPI_DOWN  2
#define EPI_HALF  3
#define GEMM_SMEM (3*32768)

template<int NITER, int EPI, bool GATHER, bool ESEL>
__global__ __launch_bounds__(256)
void k_gemm(const __half* __restrict__ A0, int lda,
            const __half* __restrict__ B0, const __half* __restrict__ B1,
            const __half* __restrict__ B2,
            long bstride, int ldb,
            void* __restrict__ C0v, void* __restrict__ C1v, void* __restrict__ C2v,
            int ldc,
            const float* __restrict__ resid, float* __restrict__ Cdual)
{
    constexpr int S = 3;
    int mt = blockIdx.y, nt = blockIdx.x;
    if (ESEL && mt*128 >= g_totalrows) return;
    const __half* Bh = (blockIdx.z==0) ? B0 : ((blockIdx.z==1) ? B1 : B2);
    void* Cv = (blockIdx.z==0) ? C0v : ((blockIdx.z==1) ? C1v : C2v);
    if (ESEL) Bh += (long)g_rowexp[mt*128] * bstride;

    extern __shared__ __align__(128) char sm_[];
    uint32_t sbase = smem_u32_(sm_);

    int tid = threadIdx.x, lane = tid & 31, wid = tid >> 5;
    int warp_m = wid & 3, warp_n = wid >> 2;

    int lrow = tid >> 1;
    int lc0  = (tid & 1) * 4;
    const __half* asrc;
    bool avalid = true;
    if (GATHER){
        int tok = g_rowtok[mt*128 + lrow];
        avalid = (tok >= 0);
        asrc = A0 + (avalid ? (size_t)tok * lda : 0);
    } else {
        asrc = A0 + (size_t)(mt*128 + lrow) * lda;
    }
    const __half* bsrc = Bh + (size_t)(nt*128 + lrow) * ldb;
    int asz = avalid ? 16 : 0;
    uint32_t arow_s = sbase + lrow*128;
    uint32_t brow_s = arow_s + 16384;

    auto stg = [&](int it){
        int stage = it % S;
        uint32_t so = (uint32_t)stage * 32768u;
        const char* ag = (const char*)(asrc + it*64);
        const char* bg = (const char*)(bsrc + it*64);
        #pragma unroll
        for (int i = 0; i < 4; i++){
            int c = lc0 + i;
            uint32_t sw = (uint32_t)((c ^ (lrow & 7)) * 16);
            cp16_(arow_s + so + sw, ag + c*16, asz);
            cp16_(brow_s + so + sw, bg + c*16, 16);
        }
    };

    float acc[2][8][4];
    #pragma unroll
    for (int i=0;i<2;i++)
        #pragma unroll
        for (int j=0;j<8;j++)
            #pragma unroll
            for (int k=0;k<4;k++) acc[i][j][k]=0.f;

    #pragma unroll
    for (int it = 0; it < S-1; it++){ stg(it); CP_COMMIT(); }

    int a_rlo = (lane & 15);
    int a_chk = (lane >> 4);
    int b_rlo = (lane & 7) + ((lane & 16) ? 8 : 0);
    int b_chk = (lane >> 3) & 1;

    for (int it = 0; it < NITER; it++){
        CP_WAIT(S-2);
        __syncthreads();
        if (it + S-1 < NITER) stg(it + S-1);
        CP_COMMIT();

        uint32_t so = (uint32_t)(it % S) * 32768u;
        uint32_t abase = sbase + so;
        uint32_t bbase = abase + 16384;

        #pragma unroll
        for (int ks = 0; ks < 4; ks++){
            uint32_t a[2][4];
            #pragma unroll
            for (int mtile = 0; mtile < 2; mtile++){
                int row = warp_m*32 + mtile*16 + a_rlo;
                int chunk = 2*ks + a_chk;
                uint32_t addr = abase + row*128 + ((chunk ^ (row & 7)) * 16);
                LDSM_X4(a[mtile][0], a[mtile][1], a[mtile][2], a[mtile][3], addr);
            }
            uint32_t b[8][2];
            #pragma unroll
            for (int n2 = 0; n2 < 4; n2++){
                int row = warp_n*64 + n2*16 + b_rlo;
                int chunk = 2*ks + b_chk;
                uint32_t addr = bbase + row*128 + ((chunk ^ (row & 7)) * 16);
                uint32_t r0,r1,r2,r3;
                LDSM_X4(r0, r1, r2, r3, addr);
                b[2*n2][0]=r0; b[2*n2][1]=r1;
                b[2*n2+1][0]=r2; b[2*n2+1][1]=r3;
            }
            #pragma unroll
            for (int mtile = 0; mtile < 2; mtile++)
                #pragma unroll
                for (int n8 = 0; n8 < 8; n8++)
                    MMA16816(acc[mtile][n8], a[mtile], b[n8]);
        }
        __syncthreads();
    }

    // ---- epilogue ----
    int m0 = mt*128 + warp_m*32;
    int n0 = nt*128 + warp_n*64;
    int gq = lane >> 2, tq = lane & 3;
    #pragma unroll
    for (int mtile = 0; mtile < 2; mtile++){
        int r_lo = m0 + mtile*16 + gq;
        int r_hi = r_lo + 8;
        if (EPI == EPI_DOWN){
            float* C = (float*)Cv;
            int tok_lo = g_rowtok[r_lo], tok_hi = g_rowtok[r_hi];
            float gl = g_rowgate[r_lo], gh = g_rowgate[r_hi];
            #pragma unroll
            for (int n8 = 0; n8 < 8; n8++){
                int col = n0 + n8*8 + tq*2;
                if (tok_lo >= 0){
                    size_t o = (size_t)tok_lo*ldc + col;
                    atomicAdd(&C[o],   gl*acc[mtile][n8][0]);
                    atomicAdd(&C[o+1], gl*acc[mtile][n8][1]);
                }
                if (tok_hi >= 0){
                    size_t o = (size_t)tok_hi*ldc + col;
                    atomicAdd(&C[o],   gh*acc[mtile][n8][2]);
                    atomicAdd(&C[o+1], gh*acc[mtile][n8][3]);
                }
            }
        } else if (EPI == EPI_RESID){
            float* C = (float*)Cv;
            #pragma unroll
            for (int n8 = 0; n8 < 8; n8++){
                int col = n0 + n8*8 + tq*2;
                size_t o_lo = (size_t)r_lo*ldc + col;
                size_t o_hi = (size_t)r_hi*ldc + col;
                float2 rv0 = *(const float2*)(resid + o_lo);
                float2 rv1 = *(const float2*)(resid + o_hi);
                float2 v0, v1;
                v0.x = acc[mtile][n8][0] + rv0.x;
                v0.y = acc[mtile][n8][1] + rv0.y;
                v1.x = acc[mtile][n8][2] + rv1.x;
                v1.y = acc[mtile][n8][3] + rv1.y;
                *(float2*)(C + o_lo) = v0;
                *(float2*)(C + o_hi) = v1;
                *(float2*)(Cdual + o_lo) = v0;
                *(float2*)(Cdual + o_hi) = v1;
            }
        } else if (EPI == EPI_HALF){
            __half* Ch = (__half*)Cv;
            #pragma unroll
            for (int n8 = 0; n8 < 8; n8++){
                int col = n0 + n8*8 + tq*2;
                __half2 v0 = __floats2half2_rn(acc[mtile][n8][0], acc[mtile][n8][1]);
                __half2 v1 = __floats2half2_rn(acc[mtile][n8][2], acc[mtile][n8][3]);
                *(__half2*)(Ch + (size_t)r_lo*ldc + col) = v0;
                *(__half2*)(Ch + (size_t)r_hi*ldc + col) = v1;
            }
        } else {
            float* C = (float*)Cv;
            #pragma unroll
            for (int n8 = 0; n8 < 8; n8++){
                int col = n0 + n8*8 + tq*2;
                float2 v0, v1;
                v0.x = acc[mtile][n8][0]; v0.y = acc[mtile][n8][1];
                v1.x = acc[mtile][n8][2]; v1.y = acc[mtile][n8][3];
                *(float2*)(C + (size_t)r_lo*ldc + col) = v0;
                *(float2*)(C + (size_t)r_hi*ldc + col) = v1;
            }
        }
    }
}

// ============================ RoPE / attention ===============================
// blockIdx.y==0 -> Q, ==1 -> K
__global__ void k_rope(float* __restrict__ q, float* __restrict__ kk) {
    int idx = blockIdx.x*blockDim.x + threadIdx.x;
    if (idx >= Tn*NHn*32) return;
    float* dst = blockIdx.y ? kk : q;
    int i = idx & 31;
    int t = idx >> 9;
    int h = (idx >> 5) & (NHn-1);
    int s = t & (Sn-1);
    float invf = powf(10000.f, -((float)(2*i)) * (1.f/(float)HDn));
    float fr = (float)s * invf;
    float c, sn;
    sincosf(fr, &sn, &c);
    float* p = dst + (size_t)t*Dn + h*HDn + i;
    float v1 = p[0], v2 = p[32];
    p[0]  = v1*c - v2*sn;
    p[32] = v2*c + v1*sn;
}

__global__ __launch_bounds__(256)
void k_attn(const float* __restrict__ Q, const float* __restrict__ Kg,
            const float* __restrict__ V, __half* __restrict__ O)
{
    __shared__ float Qs [64*64];
    __shared__ float KVs[64*64];
    __shared__ float Ps [64*64];
    int bh = blockIdx.x;
    int qt = blockIdx.y;
    int b = bh >> 4, h = bh & 15;
    int tid = threadIdx.x;
    int ty = tid >> 4, tx = tid & 15;
    size_t base = ((size_t)b*Sn)*Dn + (size_t)h*HDn;
    int q0 = qt*64;
    #pragma unroll
    for (int rep=0;rep<4;rep++){
        int lin = tid + rep*256;
        int r = lin >> 4, c = (lin & 15)*4;
        *(float4*)&Qs[r*64+c] = *(const float4*)(Q + base + (size_t)(q0+r)*Dn + c);
    }
    float acc[4][4];
    float mrow[4], lrow[4];
    #pragma unroll
    for (int i=0;i<4;i++){
        mrow[i] = -1e30f; lrow[i] = 0.f;
        #pragma unroll
        for (int j=0;j<4;j++) acc[i][j]=0.f;
    }
    __syncthreads();
    for (int kt=0; kt<=qt; kt++){
        int k0 = kt*64;
        #pragma unroll
        for (int rep=0;rep<4;rep++){
            int lin = tid + rep*256;
            int r = lin >> 4, c = (lin & 15)*4;
            float4 kv = *(const float4*)(Kg + base + (size_t)(k0+r)*Dn + c);
            KVs[(c+0)*64 + r] = kv.x;
            KVs[(c+1)*64 + r] = kv.y;
            KVs[(c+2)*64 + r] = kv.z;
            KVs[(c+3)*64 + r] = kv.w;
        }
        __syncthreads();
        float s[4][4];
        #pragma unroll
        for (int i=0;i<4;i++)
            #pragma unroll
            for (int j=0;j<4;j++) s[i][j]=0.f;
        #pragma unroll 4
        for (int d=0; d<64; d++){
            float qa[4], kb[4];
            #pragma unroll
            for (int i=0;i<4;i++) qa[i] = Qs[(ty*4+i)*64 + d];
            #pragma unroll
            for (int j=0;j<4;j++) kb[j] = KVs[d*64 + tx*4 + j];
            #pragma unroll
            for (int i=0;i<4;i++)
                #pragma unroll
                for (int j=0;j<4;j++) s[i][j] = fmaf(qa[i], kb[j], s[i][j]);
        }
        #pragma unroll
        for (int i=0;i<4;i++){
            int qq = q0 + ty*4 + i;
            #pragma unroll
            for (int j=0;j<4;j++){
                int kk = k0 + tx*4 + j;
                s[i][j] = (kk <= qq) ? s[i][j]*0.125f : -1e30f;
            }
        }
        #pragma unroll
        for (int i=0;i<4;i++){
            float mt = fmaxf(fmaxf(s[i][0],s[i][1]), fmaxf(s[i][2],s[i][3]));
            #pragma unroll
            for (int o=8;o;o>>=1) mt = fmaxf(mt, __shfl_xor_sync(0xffffffffu, mt, o));
            float mn = fmaxf(mrow[i], mt);
            float corr = __expf(mrow[i] - mn);
            float rs = 0.f;
            #pragma unroll
            for (int j=0;j<4;j++){ float p = __expf(s[i][j]-mn); s[i][j]=p; rs+=p; }
            #pragma unroll
            for (int o=8;o;o>>=1) rs += __shfl_xor_sync(0xffffffffu, rs, o);
            lrow[i] = lrow[i]*corr + rs;
            mrow[i] = mn;
            #pragma unroll
            for (int j=0;j<4;j++) acc[i][j] *= corr;
            #pragma unroll
            for (int j=0;j<4;j++) Ps[(ty*4+i)*64 + tx*4+j] = s[i][j];
        }
        __syncthreads();
        #pragma unroll
        for (int rep=0;rep<4;rep++){
            int lin = tid + rep*256;
            int r = lin >> 4, c = (lin & 15)*4;
            *(float4*)&KVs[r*64+c] = *(const float4*)(V + base + (size_t)(k0+r)*Dn + c);
        }
        __syncthreads();
        #pragma unroll 4
        for (int kv=0; kv<64; kv++){
            float pv[4], vv[4];
            #pragma unroll
            for (int i=0;i<4;i++) pv[i] = Ps[(ty*4+i)*64 + kv];
            #pragma unroll
            for (int j=0;j<4;j++) vv[j] = KVs[kv*64 + tx*4 + j];
            #pragma unroll
            for (int i=0;i<4;i++)
                #pragma unroll
                for (int j=0;j<4;j++) acc[i][j] = fmaf(pv[i], vv[j], acc[i][j]);
        }
        __syncthreads();
    }
    #pragma unroll
    for (int i=0;i<4;i++){
        float inv = 1.f/lrow[i];
        size_t o = base + (size_t)(q0+ty*4+i)*Dn + tx*4;
        __half2 p0 = __floats2half2_rn(acc[i][0]*inv, acc[i][1]*inv);
        __half2 p1 = __floats2half2_rn(acc[i][2]*inv, acc[i][3]*inv);
        *(__half2*)(O + o)     = p0;
        *(__half2*)(O + o + 2) = p1;
    }
}

// =============================== gating / MoE ================================
__global__ void k_gate(const float* __restrict__ xn, const float* __restrict__ gw)
{
    int t = blockIdx.x;
    int w = threadIdx.x >> 5, lane = threadIdx.x & 31;
    const float* xr = xn + (size_t)t * Dn;
    const float* gr = gw + (size_t)w * Dn;
    float acc = 0.f;
    for (int d = lane; d < Dn; d += 32) acc = fmaf(xr[d], gr[d], acc);
    #pragma unroll
    for (int o=16;o;o>>=1) acc += __shfl_xor_sync(0xffffffffu, acc, o);
    __shared__ float lg[En];
    if (lane == 0) lg[w] = acc;
    __syncthreads();
    if (threadIdx.x == 0){
        int i1 = 0;
        for (int e=1;e<En;e++) if (lg[e] > lg[i1]) i1 = e;
        int i2 = -1;
        for (int e=0;e<En;e++){
            if (e == i1) continue;
            if (i2 < 0 || lg[e] > lg[i2]) i2 = e;
        }
        float l1 = lg[i1], l2 = lg[i2];
        float e2 = expf(l2 - l1);
        float inv = 1.f/(1.f + e2);
        float gv1 = inv, gv2 = e2*inv;
        g_expid[t*2]   = i1; g_expid[t*2+1]   = i2;
        g_gateval[t*2] = gv1; g_gateval[t*2+1] = gv2;
        atomicAdd(&g_cnt[i1], 1); atomicAdd(&g_cnt[i2], 1);
        atomicAdd(&g_gsum[i1], gv1); atomicAdd(&g_gsum[i2], gv2);
        float mx = lg[0];
        for (int e=1;e<En;e++) mx = fmaxf(mx, lg[e]);
        float pe[En]; float se = 0.f;
        for (int e=0;e<En;e++){ pe[e] = expf(lg[e]-mx); se += pe[e]; }
        float pinv = 1.f/se;
        for (int e=0;e<En;e++) atomicAdd(&g_psum[e], pe[e]*pinv);
    }
}

__global__ void k_offsets(float* __restrict__ out, int write_aux)
{
    __shared__ int soff[En+1];
    if (threadIdx.x == 0){
        int tot = 0;
        for (int e=0;e<En;e++){
            soff[e] = tot;
            g_cursor[e] = tot;
            tot += ((g_cnt[e] + 127) >> 7) << 7;
        }
        soff[En] = tot;
        g_totalrows = tot;
        if (write_aux){
            float sacc = 0.f;
            for (int e=0;e<En;e++) sacc += g_gsum[e]*g_psum[e];
            out[(size_t)Tn*Dn] = (float)En * sacc / ((float)Tn*(float)Tn);
        }
    }
    __syncthreads();
    int tot = soff[En];
    for (int r = threadIdx.x; r < tot; r += blockDim.x){
        int e = 0;
        while (e+1 < En && r >= soff[e+1]) e++;
        g_rowexp[r] = e;
        g_rowtok[r] = -1;
    }
}

__global__ void k_scatter()
{
    int t = blockIdx.x*blockDim.x + threadIdx.x;
    if (t >= Tn) return;
    #pragma unroll
    for (int k=0;k<2;k++){
        int e = g_expid[t*2+k];
        int pos = atomicAdd(&g_cursor[e], 1);
        g_rowtok[pos] = t;
        g_rowgate[pos] = g_gateval[t*2+k];
    }
}

// H = silu(G) * U, fp16 in -> fp16 out
__global__ void k_silumul()
{
    size_t i4 = ((size_t)blockIdx.x*blockDim.x + threadIdx.x) * 4;
    size_t n = (size_t)g_totalrows * HIDn;
    if (i4 >= n) return;
    uint2 gp = *(uint2*)&g_GBh[i4];
    uint2 up = *(uint2*)&g_UBh[i4];
    __half2 g0 = *reinterpret_cast<__half2*>(&gp.x);
    __half2 g1 = *reinterpret_cast<__half2*>(&gp.y);
    __half2 u0 = *reinterpret_cast<__half2*>(&up.x);
    __half2 u1 = *reinterpret_cast<__half2*>(&up.y);
    float gx = __low2float(g0),  gy = __high2float(g0);
    float gz = __low2float(g1),  gw_ = __high2float(g1);
    float ux = __low2float(u0),  uy = __high2float(u0);
    float uz = __low2float(u1),  uw = __high2float(u1);
    float a = (gx / (1.f + __expf(-gx))) * ux;
    float b = (gy / (1.f + __expf(-gy))) * uy;
    float c = (gz / (1.f + __expf(-gz))) * uz;
    float d = (gw_ / (1.f + __expf(-gw_))) * uw;
    __half2 h0 = __floats2half2_rn(a, b);
    __half2 h1 = __floats2half2_rn(c, d);
    uint2 o;
    o.x = *reinterpret_cast<uint32_t*>(&h0);
    o.y = *reinterpret_cast<uint32_t*>(&h1);
    *(uint2*)&g_Hh[i4] = o;
}

// ---------------------------------------------------------------------------
extern "C" void kernel_launch(void* const* d_in, const int* in_sizes, int n_in,
                              void* d_out, int out_size)
{
    (void)in_sizes; (void)n_in;
    const float* x   = (const float*)d_in[0];
    const float* wq  = (const float*)d_in[1];
    const float* wk  = (const float*)d_in[2];
    const float* wv  = (const float*)d_in[3];
    const float* wo  = (const float*)d_in[4];
    const float* anw = (const float*)d_in[5];
    const float* fnw = (const float*)d_in[6];
    const float* gw  = (const float*)d_in[7];
    const float* wge = (const float*)d_in[8];
    const float* wue = (const float*)d_in[9];
    const float* wde = (const float*)d_in[10];
    float* out = (float*)d_out;

    float *pQ,*pK,*pV,*pH,*pXN2;
    __half *pXNh,*pATTh,*pXN2h,*pHh,*pGh,*pUh;
    __half *pWqh,*pWkh,*pWvh,*pWoh,*pWgeh,*pWueh,*pWdeh;
    cudaGetSymbolAddress((void**)&pQ,    g_Qb);
    cudaGetSymbolAddress((void**)&pK,    g_Kb);
    cudaGetSymbolAddress((void**)&pV,    g_Vb);
    cudaGetSymbolAddress((void**)&pH,    g_Hb);
    cudaGetSymbolAddress((void**)&pXN2,  g_XN2);
    cudaGetSymbolAddress((void**)&pGh,   g_GBh);
    cudaGetSymbolAddress((void**)&pUh,   g_UBh);
    cudaGetSymbolAddress((void**)&pXNh,  g_XNh);
    cudaGetSymbolAddress((void**)&pATTh, g_ATTh);
    cudaGetSymbolAddress((void**)&pXN2h, g_XN2h);
    cudaGetSymbolAddress((void**)&pHh,   g_Hh);
    cudaGetSymbolAddress((void**)&pWqh,  g_Wqh);
    cudaGetSymbolAddress((void**)&pWkh,  g_Wkh);
    cudaGetSymbolAddress((void**)&pWvh,  g_Wvh);
    cudaGetSymbolAddress((void**)&pWoh,  g_Woh);
    cudaGetSymbolAddress((void**)&pWgeh, g_Wgeh);
    cudaGetSymbolAddress((void**)&pWueh, g_Wueh);
    cudaGetSymbolAddress((void**)&pWdeh, g_Wdeh);

    cudaFuncSetAttribute(k_gemm<16,EPI_PLAIN,false,false>,
                         cudaFuncAttributeMaxDynamicSharedMemorySize, GEMM_SMEM);
    cudaFuncSetAttribute(k_gemm<16,EPI_RESID,false,false>,
                         cudaFuncAttributeMaxDynamicSharedMemorySize, GEMM_SMEM);
    cudaFuncSetAttribute(k_gemm<16,EPI_HALF,true,true>,
                         cudaFuncAttributeMaxDynamicSharedMemorySize, GEMM_SMEM);
    cudaFuncSetAttribute(k_gemm<64,EPI_DOWN,false,true>,
                         cudaFuncAttributeMaxDynamicSharedMemorySize, GEMM_SMEM);

    // side stream for expert-weight conversion, overlapped with attention path
    static cudaStream_t s2 = nullptr;
    static cudaEvent_t evFork = nullptr, evJoin = nullptr;
    if (!s2){
        cudaStreamCreateWithFlags(&s2, cudaStreamNonBlocking);
        cudaEventCreateWithFlags(&evFork, cudaEventDisableTiming);
        cudaEventCreateWithFlags(&evJoin, cudaEventDisableTiming);
    }

    // launch #0
    k_reset<<<1, 32>>>();

    // ---- fork: expert weight conversions on s2 (launches #1, #2) ----
    cudaEventRecord(evFork, 0);
    cudaStreamWaitEvent(s2, evFork, 0);
    {
        int ne4 = En*HIDn*(Dn/4), blk = 256, g2 = (ne4+blk-1)/blk;
        k_f2h2<<<dim3(g2,2), blk, 0, s2>>>((const float4*)wge, (const float4*)wue,
                                           (uint2*)pWgeh, (uint2*)pWueh, ne4);
        k_f2h<<<g2, blk, 0, s2>>>((const float4*)wde, (uint2*)pWdeh, ne4);
    }
    cudaEventRecord(evJoin, s2);

    // ---- main stream ----
    // launch #3: all 4 QKV/O weight conversions in one kernel
    {
        int n4 = Dn*Dn/4, blk = 256, g1 = (n4+blk-1)/blk;
        k_f2h4<<<dim3(g1,4), blk>>>((const float4*)wq, (const float4*)wk,
                                    (const float4*)wv, (const float4*)wo,
                                    (uint2*)pWqh, (uint2*)pWkh,
                                    (uint2*)pWvh, (uint2*)pWoh, n4);
    }

    // launch #4
    k_rmsnorm<<<Tn, 256>>>(x, anw, nullptr, pXNh);

    // launch #5 (ncu -s 5 lands HERE): QKV GEMM
    k_gemm<16,EPI_PLAIN,false,false><<<dim3(8,16,3), 256, GEMM_SMEM>>>(
        pXNh, Dn, pWqh, pWkh, pWvh, 0, Dn, pQ, pK, pV, Dn, nullptr, nullptr);

    int nrope = Tn*NHn*32;
    k_rope<<<dim3(nrope/256, 2), 256>>>(pQ, pK);

    k_attn<<<dim3(Bn*NHn, Sn/64), 256>>>(pQ, pK, pV, pATTh);

    k_gemm<16,EPI_RESID,false,false><<<dim3(8,16,1), 256, GEMM_SMEM>>>(
        pATTh, Dn, pWoh, pWoh, pWoh, 0, Dn, pH, pH, pH, Dn, x, out);

    k_rmsnorm<<<Tn, 256>>>(pH, fnw, pXN2, pXN2h);

    k_gate<<<Tn, 256>>>(pXN2, gw);
    int write_aux = (out_size > Tn*Dn) ? 1 : 0;
    k_offsets<<<1, 256>>>(out, write_aux);
    k_scatter<<<(Tn+255)/256, 256>>>();

    // ---- join: expert GEMMs need the converted weights ----
    cudaStreamWaitEvent(0, evJoin, 0);

    // gate/up GEMMs -> fp16 G/U buffers
    k_gemm<16,EPI_HALF,true,true><<<dim3(32, MAXROWS/128, 2), 256, GEMM_SMEM>>>(
        pXN2h, Dn, pWgeh, pWueh, pWueh, (long)HIDn*Dn, Dn, pGh, pUh, pUh, HIDn,
        nullptr, nullptr);

    k_silumul<<<(MAXROWS*(HIDn/4))/256, 256>>>();

    k_gemm<64,EPI_DOWN,false,true><<<dim3(8, MAXROWS/128, 1), 256, GEMM_SMEM>>>(
        pHh, HIDn, pWdeh, pWdeh, pWdeh, (long)Dn*HIDn, HIDn, out, out, out, Dn,
        nullptr, nullptr);
}

// round 9
// speedup vs baseline: 1.8420x; 1.2264x over previous
#include <cuda_runtime.h>
#include <cuda_fp16.h>
#include <math.h>
#include <stdint.h>

// Problem constants
#define Bn 2
#define Sn 1024
#define Dn 1024
#define NHn 16
#define HDn 64
#define En 8
#define HIDn 4096
#define Tn (Bn*Sn)          // 2048 tokens
#define MAXROWS 5248        // >= 4096 assignments + 8*127 padding, mult of 128

// ---------------- scratch (static device globals; no allocation) -------------
static __device__ __half g_XNh [Tn*Dn];
static __device__ float  g_Qb  [Tn*Dn];
static __device__ float  g_Kb  [Tn*Dn];
static __device__ float  g_Vb  [Tn*Dn];
static __device__ __half g_Qh  [Tn*Dn];
static __device__ __half g_Kh  [Tn*Dn];
static __device__ __half g_Vt  [(size_t)Bn*NHn*HDn*Sn];
static __device__ __half g_ATTh[Tn*Dn];
static __device__ float  g_Hb  [Tn*Dn];
static __device__ float  g_XN2 [Tn*Dn];
static __device__ __half g_XN2h[Tn*Dn];
static __device__ __half g_GBh [(size_t)MAXROWS*HIDn];
static __device__ __half g_UBh [(size_t)MAXROWS*HIDn];
static __device__ __half g_Hh  [(size_t)MAXROWS*HIDn];
// fp16 weights
static __device__ __half g_Wqh[Dn*Dn];
static __device__ __half g_Wkh[Dn*Dn];
static __device__ __half g_Wvh[Dn*Dn];
static __device__ __half g_Woh[Dn*Dn];
static __device__ __half g_Wgeh[(size_t)En*HIDn*Dn];
static __device__ __half g_Wueh[(size_t)En*HIDn*Dn];
static __device__ __half g_Wdeh[(size_t)En*Dn*HIDn];
// routing
static __device__ int   g_cnt[En];
static __device__ int   g_cursor[En];
static __device__ int   g_rowtok[MAXROWS];
static __device__ int   g_rowexp[MAXROWS];
static __device__ float g_rowgate[MAXROWS];
static __device__ int   g_totalrows;
static __device__ float g_gsum[En];
static __device__ float g_psum[En];
static __device__ int   g_expid[Tn*2];
static __device__ float g_gateval[Tn*2];

// ======================= PTX helpers =========================================
static __device__ __forceinline__ uint32_t smem_u32_(const void* p){
    uint32_t a;
    asm("{ .reg .u64 t; cvta.to.shared.u64 t, %1; cvt.u32.u64 %0, t; }"
        : "=r"(a) : "l"(p));
    return a;
}

#define LDSM_X4(r0,r1,r2,r3,addr) \
    asm volatile("ldmatrix.sync.aligned.m8n8.x4.shared.b16 {%0,%1,%2,%3}, [%4];" \
        : "=r"(r0),"=r"(r1),"=r"(r2),"=r"(r3) : "r"(addr))

#define MMA16816(c,a,b) \
    asm volatile("mma.sync.aligned.m16n8k16.row.col.f32.f16.f16.f32 " \
        "{%0,%1,%2,%3}, {%4,%5,%6,%7}, {%8,%9}, {%0,%1,%2,%3};" \
        : "+f"((c)[0]),"+f"((c)[1]),"+f"((c)[2]),"+f"((c)[3]) \
        : "r"((a)[0]),"r"((a)[1]),"r"((a)[2]),"r"((a)[3]), \
          "r"((b)[0]),"r"((b)[1]))

#define CP_COMMIT() asm volatile("cp.async.commit_group;" ::: "memory")
#define CP_WAIT(N)  asm volatile("cp.async.wait_group %0;" :: "n"(N) : "memory")

static __device__ __forceinline__ void cp16_(uint32_t dst, const void* src, int srcsize){
    asm volatile("cp.async.cg.shared.global [%0], [%1], 16, %2;"
        :: "r"(dst), "l"((unsigned long long)__cvta_generic_to_global(src)),
           "r"(srcsize) : "memory");
}

// ============================== small kernels ================================
__global__ void k_reset() {
    int i = threadIdx.x;
    if (i < En) { g_cnt[i] = 0; g_gsum[i] = 0.f; g_psum[i] = 0.f; }
}

static __device__ __forceinline__ void f2h_one_(const float4* s, uint2* d, int i){
    float4 v = s[i];
    __half2 h0 = __floats2half2_rn(v.x, v.y);
    __half2 h1 = __floats2half2_rn(v.z, v.w);
    uint2 o;
    o.x = *reinterpret_cast<uint32_t*>(&h0);
    o.y = *reinterpret_cast<uint32_t*>(&h1);
    d[i] = o;
}

__global__ void k_f2h2(const float4* __restrict__ s0, const float4* __restrict__ s1,
                       uint2* __restrict__ d0, uint2* __restrict__ d1, int n4){
    int i = blockIdx.x*blockDim.x + threadIdx.x;
    if (i >= n4) return;
    if (blockIdx.y == 0) f2h_one_(s0, d0, i);
    else                 f2h_one_(s1, d1, i);
}

__global__ void k_f2h4(const float4* __restrict__ s0, const float4* __restrict__ s1,
                       const float4* __restrict__ s2p, const float4* __restrict__ s3,
                       uint2* __restrict__ d0, uint2* __restrict__ d1,
                       uint2* __restrict__ d2, uint2* __restrict__ d3, int n4){
    int i = blockIdx.x*blockDim.x + threadIdx.x;
    if (i >= n4) return;
    switch (blockIdx.y){
        case 0: f2h_one_(s0, d0, i); break;
        case 1: f2h_one_(s1, d1, i); break;
        case 2: f2h_one_(s2p, d2, i); break;
        default: f2h_one_(s3, d3, i); break;
    }
}

__global__ void k_f2h(const float4* __restrict__ s, uint2* __restrict__ d, int n4){
    int i = blockIdx.x*blockDim.x + threadIdx.x;
    if (i >= n4) return;
    f2h_one_(s, d, i);
}

__global__ void k_rmsnorm(const float* __restrict__ x, const float* __restrict__ w,
                          float* __restrict__ y, __half* __restrict__ yh) {
    int t = blockIdx.x;
    const float* xr = x + (size_t)t * Dn;
    int base = threadIdx.x * 4;
    float4 xv = *(const float4*)(xr + base);
    float ss = xv.x*xv.x + xv.y*xv.y + xv.z*xv.z + xv.w*xv.w;
    #pragma unroll
    for (int o = 16; o; o >>= 1) ss += __shfl_xor_sync(0xffffffffu, ss, o);
    __shared__ float ws[8];
    if ((threadIdx.x & 31) == 0) ws[threadIdx.x >> 5] = ss;
    __syncthreads();
    float tot = ws[0]+ws[1]+ws[2]+ws[3]+ws[4]+ws[5]+ws[6]+ws[7];
    float sc = rsqrtf(tot * (1.f/(float)Dn) + 1e-6f);
    float4 wv = *(const float4*)(w + base);
    float4 o4;
    o4.x = wv.x*xv.x*sc; o4.y = wv.y*xv.y*sc;
    o4.z = wv.z*xv.z*sc; o4.w = wv.w*xv.w*sc;
    if (y) *(float4*)(y + (size_t)t*Dn + base) = o4;
    __half2 h0 = __floats2half2_rn(o4.x, o4.y);
    __half2 h1 = __floats2half2_rn(o4.z, o4.w);
    uint2 ho;
    ho.x = *reinterpret_cast<uint32_t*>(&h0);
    ho.y = *reinterpret_cast<uint32_t*>(&h1);
    *(uint2*)(yh + (size_t)t*Dn + base) = ho;
}

// ===================== mma.sync GEMM (HMMA tensor path) ======================
#define EPI_PLAIN 0
#define EPI_RESID 1
#define EPI_DOWN  2
#define EPI_HALF  3
#define GEMM_SMEM (3*32768)

template<int NITER, int EPI, bool GATHER, bool ESEL>
__global__ __launch_bounds__(256)
void k_gemm(const __half* __restrict__ A0, int lda,
            const __half* __restrict__ B0, const __half* __restrict__ B1,
            const __half* __restrict__ B2,
            long bstride, int ldb,
            void* __restrict__ C0v, void* __restrict__ C1v, void* __restrict__ C2v,
            int ldc,
            const float* __restrict__ resid, float* __restrict__ Cdual)
{
    constexpr int S = 3;
    int mt = blockIdx.y, nt = blockIdx.x;
    if (ESEL && mt*128 >= g_totalrows) return;
    const __half* Bh = (blockIdx.z==0) ? B0 : ((blockIdx.z==1) ? B1 : B2);
    void* Cv = (blockIdx.z==0) ? C0v : ((blockIdx.z==1) ? C1v : C2v);
    if (ESEL) Bh += (long)g_rowexp[mt*128] * bstride;

    extern __shared__ __align__(128) char sm_[];
    uint32_t sbase = smem_u32_(sm_);

    int tid = threadIdx.x, lane = tid & 31, wid = tid >> 5;
    int warp_m = wid & 3, warp_n = wid >> 2;

    int lrow = tid >> 1;
    int lc0  = (tid & 1) * 4;
    const __half* asrc;
    bool avalid = true;
    if (GATHER){
        int tok = g_rowtok[mt*128 + lrow];
        avalid = (tok >= 0);
        asrc = A0 + (avalid ? (size_t)tok * lda : 0);
    } else {
        asrc = A0 + (size_t)(mt*128 + lrow) * lda;
    }
    const __half* bsrc = Bh + (size_t)(nt*128 + lrow) * ldb;
    int asz = avalid ? 16 : 0;
    uint32_t arow_s = sbase + lrow*128;
    uint32_t brow_s = arow_s + 16384;

    auto stg = [&](int it){
        int stage = it % S;
        uint32_t so = (uint32_t)stage * 32768u;
        const char* ag = (const char*)(asrc + it*64);
        const char* bg = (const char*)(bsrc + it*64);
        #pragma unroll
        for (int i = 0; i < 4; i++){
            int c = lc0 + i;
            uint32_t sw = (uint32_t)((c ^ (lrow & 7)) * 16);
            cp16_(arow_s + so + sw, ag + c*16, asz);
            cp16_(brow_s + so + sw, bg + c*16, 16);
        }
    };

    float acc[2][8][4];
    #pragma unroll
    for (int i=0;i<2;i++)
        #pragma unroll
        for (int j=0;j<8;j++)
            #pragma unroll
            for (int k=0;k<4;k++) acc[i][j][k]=0.f;

    #pragma unroll
    for (int it = 0; it < S-1; it++){ stg(it); CP_COMMIT(); }

    int a_rlo = (lane & 15);
    int a_chk = (lane >> 4);
    int b_rlo = (lane & 7) + ((lane & 16) ? 8 : 0);
    int b_chk = (lane >> 3) & 1;

    for (int it = 0; it < NITER; it++){
        CP_WAIT(S-2);
        __syncthreads();
        if (it + S-1 < NITER) stg(it + S-1);
        CP_COMMIT();

        uint32_t so = (uint32_t)(it % S) * 32768u;
        uint32_t abase = sbase + so;
        uint32_t bbase = abase + 16384;

        #pragma unroll
        for (int ks = 0; ks < 4; ks++){
            uint32_t a[2][4];
            #pragma unroll
            for (int mtile = 0; mtile < 2; mtile++){
                int row = warp_m*32 + mtile*16 + a_rlo;
                int chunk = 2*ks + a_chk;
                uint32_t addr = abase + row*128 + ((chunk ^ (row & 7)) * 16);
                LDSM_X4(a[mtile][0], a[mtile][1], a[mtile][2], a[mtile][3], addr);
            }
            uint32_t b[8][2];
            #pragma unroll
            for (int n2 = 0; n2 < 4; n2++){
                int row = warp_n*64 + n2*16 + b_rlo;
                int chunk = 2*ks + b_chk;
                uint32_t addr = bbase + row*128 + ((chunk ^ (row & 7)) * 16);
                uint32_t r0,r1,r2,r3;
                LDSM_X4(r0, r1, r2, r3, addr);
                b[2*n2][0]=r0; b[2*n2][1]=r1;
                b[2*n2+1][0]=r2; b[2*n2+1][1]=r3;
            }
            #pragma unroll
            for (int mtile = 0; mtile < 2; mtile++)
                #pragma unroll
                for (int n8 = 0; n8 < 8; n8++)
                    MMA16816(acc[mtile][n8], a[mtile], b[n8]);
        }
        __syncthreads();
    }

    // ---- epilogue ----
    int m0 = mt*128 + warp_m*32;
    int n0 = nt*128 + warp_n*64;
    int gq = lane >> 2, tq = lane & 3;
    #pragma unroll
    for (int mtile = 0; mtile < 2; mtile++){
        int r_lo = m0 + mtile*16 + gq;
        int r_hi = r_lo + 8;
        if (EPI == EPI_DOWN){
            float* C = (float*)Cv;
            int tok_lo = g_rowtok[r_lo], tok_hi = g_rowtok[r_hi];
            float gl = g_rowgate[r_lo], gh = g_rowgate[r_hi];
            #pragma unroll
            for (int n8 = 0; n8 < 8; n8++){
                int col = n0 + n8*8 + tq*2;
                if (tok_lo >= 0){
                    size_t o = (size_t)tok_lo*ldc + col;
                    atomicAdd(&C[o],   gl*acc[mtile][n8][0]);
                    atomicAdd(&C[o+1], gl*acc[mtile][n8][1]);
                }
                if (tok_hi >= 0){
                    size_t o = (size_t)tok_hi*ldc + col;
                    atomicAdd(&C[o],   gh*acc[mtile][n8][2]);
                    atomicAdd(&C[o+1], gh*acc[mtile][n8][3]);
                }
            }
        } else if (EPI == EPI_RESID){
            float* C = (float*)Cv;
            #pragma unroll
            for (int n8 = 0; n8 < 8; n8++){
                int col = n0 + n8*8 + tq*2;
                size_t o_lo = (size_t)r_lo*ldc + col;
                size_t o_hi = (size_t)r_hi*ldc + col;
                float2 rv0 = *(const float2*)(resid + o_lo);
                float2 rv1 = *(const float2*)(resid + o_hi);
                float2 v0, v1;
                v0.x = acc[mtile][n8][0] + rv0.x;
                v0.y = acc[mtile][n8][1] + rv0.y;
                v1.x = acc[mtile][n8][2] + rv1.x;
                v1.y = acc[mtile][n8][3] + rv1.y;
                *(float2*)(C + o_lo) = v0;
                *(float2*)(C + o_hi) = v1;
                *(float2*)(Cdual + o_lo) = v0;
                *(float2*)(Cdual + o_hi) = v1;
            }
        } else if (EPI == EPI_HALF){
            __half* Ch = (__half*)Cv;
            #pragma unroll
            for (int n8 = 0; n8 < 8; n8++){
                int col = n0 + n8*8 + tq*2;
                __half2 v0 = __floats2half2_rn(acc[mtile][n8][0], acc[mtile][n8][1]);
                __half2 v1 = __floats2half2_rn(acc[mtile][n8][2], acc[mtile][n8][3]);
                *(__half2*)(Ch + (size_t)r_lo*ldc + col) = v0;
                *(__half2*)(Ch + (size_t)r_hi*ldc + col) = v1;
            }
        } else {
            float* C = (float*)Cv;
            #pragma unroll
            for (int n8 = 0; n8 < 8; n8++){
                int col = n0 + n8*8 + tq*2;
                float2 v0, v1;
                v0.x = acc[mtile][n8][0]; v0.y = acc[mtile][n8][1];
                v1.x = acc[mtile][n8][2]; v1.y = acc[mtile][n8][3];
                *(float2*)(C + (size_t)r_lo*ldc + col) = v0;
                *(float2*)(C + (size_t)r_hi*ldc + col) = v1;
            }
        }
    }
}

// ====================== RoPE (fp32 in -> fp16 out) ===========================
// blockIdx.y==0 -> Q, ==1 -> K
__global__ void k_ropeh(const float* __restrict__ q, const float* __restrict__ k,
                        __half* __restrict__ qh, __half* __restrict__ kh) {
    int idx = blockIdx.x*blockDim.x + threadIdx.x;
    if (idx >= Tn*NHn*32) return;
    const float* src = blockIdx.y ? k : q;
    __half* dst = blockIdx.y ? kh : qh;
    int i = idx & 31;
    int t = idx >> 9;
    int h = (idx >> 5) & (NHn-1);
    int s = t & (Sn-1);
    float invf = powf(10000.f, -((float)(2*i)) * (1.f/(float)HDn));
    float fr = (float)s * invf;
    float c, sn;
    sincosf(fr, &sn, &c);
    size_t o = (size_t)t*Dn + h*HDn + i;
    float v1 = src[o], v2 = src[o + 32];
    dst[o]      = __float2half(v1*c - v2*sn);
    dst[o + 32] = __float2half(v2*c + v1*sn);
}

// ============ V transpose: fp32 [t][h*64+d] -> fp16 Vt[bh][d][s] =============
__global__ void k_vtrans(const float* __restrict__ V, __half* __restrict__ Vt)
{
    __shared__ float ts[64][65];
    int bh = blockIdx.x, st = blockIdx.y;
    int b = bh >> 4, h = bh & 15;
    int tid = threadIdx.x;                 // 128 threads
    int row = tid >> 1, c0 = (tid & 1) * 32;
    const float4* src = (const float4*)(V + ((size_t)(b*Sn + st*64 + row))*Dn
                                          + h*HDn + c0);
    #pragma unroll
    for (int i = 0; i < 8; i++){
        float4 v = src[i];
        ts[row][c0 + 4*i + 0] = v.x;
        ts[row][c0 + 4*i + 1] = v.y;
        ts[row][c0 + 4*i + 2] = v.z;
        ts[row][c0 + 4*i + 3] = v.w;
    }
    __syncthreads();
    // write row d=row, keys st*64 + c0 .. +31
    __half* dst = Vt + ((size_t)bh*HDn + row)*Sn + st*64 + c0;
    #pragma unroll
    for (int i = 0; i < 32; i += 2){
        __half2 hv = __floats2half2_rn(ts[c0+i][row], ts[c0+i+1][row]);
        *(__half2*)(dst + i) = hv;
    }
}

// ================= HMMA flash attention (m16n8k16) ===========================
// 4 warps, each owns 16 query rows of a 64-query tile; 64-key iterations.
__global__ __launch_bounds__(128)
void k_attn_mma(const __half* __restrict__ Qh, const __half* __restrict__ Kh,
                const __half* __restrict__ Vt, __half* __restrict__ O)
{
    __shared__ __align__(128) char sm[3*8192];
    uint32_t qs = smem_u32_(sm);
    uint32_t ks = qs + 8192;
    uint32_t vs = qs + 16384;

    int bh = blockIdx.x;          // b*16 + h
    int qt = blockIdx.y;
    int b = bh >> 4, h = bh & 15;
    int tid = threadIdx.x, lane = tid & 31, wid = tid >> 5;
    int q0 = qt*64;

    int srow = tid >> 1, sc0 = (tid & 1) * 4;     // staging: 64 rows x 8 chunks
    int gq = lane >> 2, tq = lane & 3;
    int a_rlo = lane & 15, a_chk = lane >> 4;
    int b_rlo = (lane & 7) + ((lane & 16) ? 8 : 0);
    int b_chk = (lane >> 3) & 1;

    // ---- stage Q tile (swizzled) ----
    {
        const uint4* src = (const uint4*)(Qh + ((size_t)(b*Sn + q0 + srow))*Dn + h*HDn);
        #pragma unroll
        for (int i = 0; i < 4; i++){
            int c = sc0 + i;
            *(uint4*)(sm + (qs - qs) + srow*128 + ((c ^ (srow & 7)) * 16)) = src[c];
        }
    }
    __syncthreads();

    // ---- Q fragments (once) ----
    uint32_t qa[4][4];
    #pragma unroll
    for (int kc = 0; kc < 4; kc++){
        int row = wid*16 + a_rlo;
        int chunk = kc*2 + a_chk;
        uint32_t addr = qs + row*128 + ((chunk ^ (row & 7)) * 16);
        LDSM_X4(qa[kc][0], qa[kc][1], qa[kc][2], qa[kc][3], addr);
    }

    float o_[8][4];
    #pragma unroll
    for (int j=0;j<8;j++)
        #pragma unroll
        for (int k=0;k<4;k++) o_[j][k]=0.f;
    float m_lo = -1e30f, m_hi = -1e30f, l_lo = 0.f, l_hi = 0.f;

    for (int kt = 0; kt <= qt; kt++){
        // ---- stage K tile + Vt tile ----
        {
            const uint4* ksrc = (const uint4*)(Kh + ((size_t)(b*Sn + kt*64 + srow))*Dn + h*HDn);
            const uint4* vsrc = (const uint4*)(Vt + ((size_t)bh*HDn + srow)*Sn + kt*64);
            #pragma unroll
            for (int i = 0; i < 4; i++){
                int c = sc0 + i;
                uint32_t sw = (uint32_t)((c ^ (srow & 7)) * 16);
                *(uint4*)(sm + 8192  + srow*128 + sw) = ksrc[c];
                *(uint4*)(sm + 16384 + srow*128 + sw) = vsrc[c];
            }
        }
        __syncthreads();

        // ---- S = Q @ K^T ----
        float s_[8][4];
        #pragma unroll
        for (int j=0;j<8;j++)
            #pragma unroll
            for (int k=0;k<4;k++) s_[j][k]=0.f;
        #pragma unroll
        for (int kc = 0; kc < 4; kc++){
            uint32_t kb[8][2];
            #pragma unroll
            for (int n2 = 0; n2 < 4; n2++){
                int row = n2*16 + b_rlo;
                int chunk = kc*2 + b_chk;
                uint32_t addr = ks + row*128 + ((chunk ^ (row & 7)) * 16);
                uint32_t r0,r1,r2,r3;
                LDSM_X4(r0, r1, r2, r3, addr);
                kb[2*n2][0]=r0; kb[2*n2][1]=r1;
                kb[2*n2+1][0]=r2; kb[2*n2+1][1]=r3;
            }
            #pragma unroll
            for (int j = 0; j < 8; j++)
                MMA16816(s_[j], qa[kc], kb[j]);
        }

        // ---- scale + causal mask ----
        int row_lo = q0 + wid*16 + gq;
        int row_hi = row_lo + 8;
        #pragma unroll
        for (int j = 0; j < 8; j++){
            int c0 = kt*64 + j*8 + tq*2;
            int c1 = c0 + 1;
            s_[j][0] = (c0 <= row_lo) ? s_[j][0]*0.125f : -1e30f;
            s_[j][1] = (c1 <= row_lo) ? s_[j][1]*0.125f : -1e30f;
            s_[j][2] = (c0 <= row_hi) ? s_[j][2]*0.125f : -1e30f;
            s_[j][3] = (c1 <= row_hi) ? s_[j][3]*0.125f : -1e30f;
        }

        // ---- online softmax (per row; quad shuffles over tq) ----
        float tm_lo = -1e30f, tm_hi = -1e30f;
        #pragma unroll
        for (int j = 0; j < 8; j++){
            tm_lo = fmaxf(tm_lo, fmaxf(s_[j][0], s_[j][1]));
            tm_hi = fmaxf(tm_hi, fmaxf(s_[j][2], s_[j][3]));
        }
        tm_lo = fmaxf(tm_lo, __shfl_xor_sync(0xffffffffu, tm_lo, 1));
        tm_lo = fmaxf(tm_lo, __shfl_xor_sync(0xffffffffu, tm_lo, 2));
        tm_hi = fmaxf(tm_hi, __shfl_xor_sync(0xffffffffu, tm_hi, 1));
        tm_hi = fmaxf(tm_hi, __shfl_xor_sync(0xffffffffu, tm_hi, 2));
        float mn_lo = fmaxf(m_lo, tm_lo);
        float mn_hi = fmaxf(m_hi, tm_hi);
        float corr_lo = __expf(m_lo - mn_lo);
        float corr_hi = __expf(m_hi - mn_hi);
        float rs_lo = 0.f, rs_hi = 0.f;
        #pragma unroll
        for (int j = 0; j < 8; j++){
            s_[j][0] = __expf(s_[j][0] - mn_lo);
            s_[j][1] = __expf(s_[j][1] - mn_lo);
            s_[j][2] = __expf(s_[j][2] - mn_hi);
            s_[j][3] = __expf(s_[j][3] - mn_hi);
            rs_lo += s_[j][0] + s_[j][1];
            rs_hi += s_[j][2] + s_[j][3];
        }
        rs_lo += __shfl_xor_sync(0xffffffffu, rs_lo, 1);
        rs_lo += __shfl_xor_sync(0xffffffffu, rs_lo, 2);
        rs_hi += __shfl_xor_sync(0xffffffffu, rs_hi, 1);
        rs_hi += __shfl_xor_sync(0xffffffffu, rs_hi, 2);
        l_lo = l_lo*corr_lo + rs_lo;
        l_hi = l_hi*corr_hi + rs_hi;
        m_lo = mn_lo; m_hi = mn_hi;
        #pragma unroll
        for (int j = 0; j < 8; j++){
            o_[j][0] *= corr_lo; o_[j][1] *= corr_lo;
            o_[j][2] *= corr_hi; o_[j][3] *= corr_hi;
        }

        // ---- P fragments (C-frag -> A-frag) ----
        uint32_t pa[4][4];
        #pragma unroll
        for (int kc = 0; kc < 4; kc++){
            __half2 h0 = __floats2half2_rn(s_[2*kc][0],   s_[2*kc][1]);
            __half2 h1 = __floats2half2_rn(s_[2*kc][2],   s_[2*kc][3]);
            __half2 h2 = __floats2half2_rn(s_[2*kc+1][0], s_[2*kc+1][1]);
            __half2 h3 = __floats2half2_rn(s_[2*kc+1][2], s_[2*kc+1][3]);
            pa[kc][0] = *reinterpret_cast<uint32_t*>(&h0);
            pa[kc][1] = *reinterpret_cast<uint32_t*>(&h1);
            pa[kc][2] = *reinterpret_cast<uint32_t*>(&h2);
            pa[kc][3] = *reinterpret_cast<uint32_t*>(&h3);
        }

        // ---- O += P @ V  (B frags from Vt rows, d-major) ----
        #pragma unroll
        for (int kc = 0; kc < 4; kc++){
            uint32_t vb[8][2];
            #pragma unroll
            for (int n2 = 0; n2 < 4; n2++){
                int row = n2*16 + b_rlo;            // d
                int chunk = kc*2 + b_chk;           // key chunk
                uint32_t addr = vs + row*128 + ((chunk ^ (row & 7)) * 16);
                uint32_t r0,r1,r2,r3;
                LDSM_X4(r0, r1, r2, r3, addr);
                vb[2*n2][0]=r0; vb[2*n2][1]=r1;
                vb[2*n2+1][0]=r2; vb[2*n2+1][1]=r3;
            }
            #pragma unroll
            for (int j = 0; j < 8; j++)
                MMA16816(o_[j], pa[kc], vb[j]);
        }
        __syncthreads();
    }

    // ---- normalize + store fp16 ----
    float inv_lo = 1.f/l_lo, inv_hi = 1.f/l_hi;
    int row_lo = q0 + wid*16 + gq;
    int row_hi = row_lo + 8;
    #pragma unroll
    for (int j = 0; j < 8; j++){
        int col = j*8 + tq*2;   // d
        __half2 v0 = __floats2half2_rn(o_[j][0]*inv_lo, o_[j][1]*inv_lo);
        __half2 v1 = __floats2half2_rn(o_[j][2]*inv_hi, o_[j][3]*inv_hi);
        *(__half2*)(O + ((size_t)(b*Sn + row_lo))*Dn + h*HDn + col) = v0;
        *(__half2*)(O + ((size_t)(b*Sn + row_hi))*Dn + h*HDn + col) = v1;
    }
}

// =============================== gating / MoE ================================
__global__ void k_gate(const float* __restrict__ xn, const float* __restrict__ gw)
{
    int t = blockIdx.x;
    int w = threadIdx.x >> 5, lane = threadIdx.x & 31;
    const float* xr = xn + (size_t)t * Dn;
    const float* gr = gw + (size_t)w * Dn;
    float acc = 0.f;
    for (int d = lane; d < Dn; d += 32) acc = fmaf(xr[d], gr[d], acc);
    #pragma unroll
    for (int o=16;o;o>>=1) acc += __shfl_xor_sync(0xffffffffu, acc, o);
    __shared__ float lg[En];
    if (lane == 0) lg[w] = acc;
    __syncthreads();
    if (threadIdx.x == 0){
        int i1 = 0;
        for (int e=1;e<En;e++) if (lg[e] > lg[i1]) i1 = e;
        int i2 = -1;
        for (int e=0;e<En;e++){
            if (e == i1) continue;
            if (i2 < 0 || lg[e] > lg[i2]) i2 = e;
        }
        float l1 = lg[i1], l2 = lg[i2];
        float e2 = expf(l2 - l1);
        float inv = 1.f/(1.f + e2);
        float gv1 = inv, gv2 = e2*inv;
        g_expid[t*2]   = i1; g_expid[t*2+1]   = i2;
        g_gateval[t*2] = gv1; g_gateval[t*2+1] = gv2;
        atomicAdd(&g_cnt[i1], 1); atomicAdd(&g_cnt[i2], 1);
        atomicAdd(&g_gsum[i1], gv1); atomicAdd(&g_gsum[i2], gv2);
        float mx = lg[0];
        for (int e=1;e<En;e++) mx = fmaxf(mx, lg[e]);
        float pe[En]; float se = 0.f;
        for (int e=0;e<En;e++){ pe[e] = expf(lg[e]-mx); se += pe[e]; }
        float pinv = 1.f/se;
        for (int e=0;e<En;e++) atomicAdd(&g_psum[e], pe[e]*pinv);
    }
}

__global__ void k_offsets(float* __restrict__ out, int write_aux)
{
    __shared__ int soff[En+1];
    if (threadIdx.x == 0){
        int tot = 0;
        for (int e=0;e<En;e++){
            soff[e] = tot;
            g_cursor[e] = tot;
            tot += ((g_cnt[e] + 127) >> 7) << 7;
        }
        soff[En] = tot;
        g_totalrows = tot;
        if (write_aux){
            float sacc = 0.f;
            for (int e=0;e<En;e++) sacc += g_gsum[e]*g_psum[e];
            out[(size_t)Tn*Dn] = (float)En * sacc / ((float)Tn*(float)Tn);
        }
    }
    __syncthreads();
    int tot = soff[En];
    for (int r = threadIdx.x; r < tot; r += blockDim.x){
        int e = 0;
        while (e+1 < En && r >= soff[e+1]) e++;
        g_rowexp[r] = e;
        g_rowtok[r] = -1;
    }
}

__global__ void k_scatter()
{
    int t = blockIdx.x*blockDim.x + threadIdx.x;
    if (t >= Tn) return;
    #pragma unroll
    for (int k=0;k<2;k++){
        int e = g_expid[t*2+k];
        int pos = atomicAdd(&g_cursor[e], 1);
        g_rowtok[pos] = t;
        g_rowgate[pos] = g_gateval[t*2+k];
    }
}

// H = silu(G) * U, fp16 in -> fp16 out
__global__ void k_silumul()
{
    size_t i4 = ((size_t)blockIdx.x*blockDim.x + threadIdx.x) * 4;
    size_t n = (size_t)g_totalrows * HIDn;
    if (i4 >= n) return;
    uint2 gp = *(uint2*)&g_GBh[i4];
    uint2 up = *(uint2*)&g_UBh[i4];
    __half2 g0 = *reinterpret_cast<__half2*>(&gp.x);
    __half2 g1 = *reinterpret_cast<__half2*>(&gp.y);
    __half2 u0 = *reinterpret_cast<__half2*>(&up.x);
    __half2 u1 = *reinterpret_cast<__half2*>(&up.y);
    float gx = __low2float(g0),  gy = __high2float(g0);
    float gz = __low2float(g1),  gw_ = __high2float(g1);
    float ux = __low2float(u0),  uy = __high2float(u0);
    float uz = __low2float(u1),  uw = __high2float(u1);
    float a = (gx / (1.f + __expf(-gx))) * ux;
    float b = (gy / (1.f + __expf(-gy))) * uy;
    float c = (gz / (1.f + __expf(-gz))) * uz;
    float d = (gw_ / (1.f + __expf(-gw_))) * uw;
    __half2 h0 = __floats2half2_rn(a, b);
    __half2 h1 = __floats2half2_rn(c, d);
    uint2 o;
    o.x = *reinterpret_cast<uint32_t*>(&h0);
    o.y = *reinterpret_cast<uint32_t*>(&h1);
    *(uint2*)&g_Hh[i4] = o;
}

// ---------------------------------------------------------------------------
extern "C" void kernel_launch(void* const* d_in, const int* in_sizes, int n_in,
                              void* d_out, int out_size)
{
    (void)in_sizes; (void)n_in;
    const float* x   = (const float*)d_in[0];
    const float* wq  = (const float*)d_in[1];
    const float* wk  = (const float*)d_in[2];
    const float* wv  = (const float*)d_in[3];
    const float* wo  = (const float*)d_in[4];
    const float* anw = (const float*)d_in[5];
    const float* fnw = (const float*)d_in[6];
    const float* gw  = (const float*)d_in[7];
    const float* wge = (const float*)d_in[8];
    const float* wue = (const float*)d_in[9];
    const float* wde = (const float*)d_in[10];
    float* out = (float*)d_out;

    float *pQ,*pK,*pV,*pH,*pXN2;
    __half *pXNh,*pATTh,*pXN2h,*pHh,*pGh,*pUh,*pQhh,*pKhh,*pVt;
    __half *pWqh,*pWkh,*pWvh,*pWoh,*pWgeh,*pWueh,*pWdeh;
    cudaGetSymbolAddress((void**)&pQ,    g_Qb);
    cudaGetSymbolAddress((void**)&pK,    g_Kb);
    cudaGetSymbolAddress((void**)&pV,    g_Vb);
    cudaGetSymbolAddress((void**)&pH,    g_Hb);
    cudaGetSymbolAddress((void**)&pXN2,  g_XN2);
    cudaGetSymbolAddress((void**)&pGh,   g_GBh);
    cudaGetSymbolAddress((void**)&pUh,   g_UBh);
    cudaGetSymbolAddress((void**)&pXNh,  g_XNh);
    cudaGetSymbolAddress((void**)&pATTh, g_ATTh);
    cudaGetSymbolAddress((void**)&pXN2h, g_XN2h);
    cudaGetSymbolAddress((void**)&pHh,   g_Hh);
    cudaGetSymbolAddress((void**)&pQhh,  g_Qh);
    cudaGetSymbolAddress((void**)&pKhh,  g_Kh);
    cudaGetSymbolAddress((void**)&pVt,   g_Vt);
    cudaGetSymbolAddress((void**)&pWqh,  g_Wqh);
    cudaGetSymbolAddress((void**)&pWkh,  g_Wkh);
    cudaGetSymbolAddress((void**)&pWvh,  g_Wvh);
    cudaGetSymbolAddress((void**)&pWoh,  g_Woh);
    cudaGetSymbolAddress((void**)&pWgeh, g_Wgeh);
    cudaGetSymbolAddress((void**)&pWueh, g_Wueh);
    cudaGetSymbolAddress((void**)&pWdeh, g_Wdeh);

    cudaFuncSetAttribute(k_gemm<16,EPI_PLAIN,false,false>,
                         cudaFuncAttributeMaxDynamicSharedMemorySize, GEMM_SMEM);
    cudaFuncSetAttribute(k_gemm<16,EPI_RESID,false,false>,
                         cudaFuncAttributeMaxDynamicSharedMemorySize, GEMM_SMEM);
    cudaFuncSetAttribute(k_gemm<16,EPI_HALF,true,true>,
                         cudaFuncAttributeMaxDynamicSharedMemorySize, GEMM_SMEM);
    cudaFuncSetAttribute(k_gemm<64,EPI_DOWN,false,true>,
                         cudaFuncAttributeMaxDynamicSharedMemorySize, GEMM_SMEM);

    // side stream for expert-weight conversion, overlapped with attention path
    static cudaStream_t s2 = nullptr;
    static cudaEvent_t evFork = nullptr, evJoin = nullptr;
    if (!s2){
        cudaStreamCreateWithFlags(&s2, cudaStreamNonBlocking);
        cudaEventCreateWithFlags(&evFork, cudaEventDisableTiming);
        cudaEventCreateWithFlags(&evJoin, cudaEventDisableTiming);
    }

    k_reset<<<1, 32>>>();

    // ---- fork: expert weight conversions on s2 ----
    cudaEventRecord(evFork, 0);
    cudaStreamWaitEvent(s2, evFork, 0);
    {
        int ne4 = En*HIDn*(Dn/4), blk = 256, g2 = (ne4+blk-1)/blk;
        k_f2h2<<<dim3(g2,2), blk, 0, s2>>>((const float4*)wge, (const float4*)wue,
                                           (uint2*)pWgeh, (uint2*)pWueh, ne4);
        k_f2h<<<g2, blk, 0, s2>>>((const float4*)wde, (uint2*)pWdeh, ne4);
    }
    cudaEventRecord(evJoin, s2);

    // ---- main stream: attention path ----
    {
        int n4 = Dn*Dn/4, blk = 256, g1 = (n4+blk-1)/blk;
        k_f2h4<<<dim3(g1,4), blk>>>((const float4*)wq, (const float4*)wk,
                                    (const float4*)wv, (const float4*)wo,
                                    (uint2*)pWqh, (uint2*)pWkh,
                                    (uint2*)pWvh, (uint2*)pWoh, n4);
    }

    k_rmsnorm<<<Tn, 256>>>(x, anw, nullptr, pXNh);

    // QKV GEMM (fp32 out, rope needs precision)
    k_gemm<16,EPI_PLAIN,false,false><<<dim3(8,16,3), 256, GEMM_SMEM>>>(
        pXNh, Dn, pWqh, pWkh, pWvh, 0, Dn, pQ, pK, pV, Dn, nullptr, nullptr);

    // RoPE -> fp16 Q/K ; V -> transposed fp16
    int nrope = Tn*NHn*32;
    k_ropeh<<<dim3(nrope/256, 2), 256>>>(pQ, pK, pQhh, pKhh);
    k_vtrans<<<dim3(Bn*NHn, Sn/64), 128>>>(pV, pVt);

    // HMMA flash attention
    k_attn_mma<<<dim3(Bn*NHn, Sn/64), 128>>>(pQhh, pKhh, pVt, pATTh);

    k_gemm<16,EPI_RESID,false,false><<<dim3(8,16,1), 256, GEMM_SMEM>>>(
        pATTh, Dn, pWoh, pWoh, pWoh, 0, Dn, pH, pH, pH, Dn, x, out);

    k_rmsnorm<<<Tn, 256>>>(pH, fnw, pXN2, pXN2h);

    k_gate<<<Tn, 256>>>(pXN2, gw);
    int write_aux = (out_size > Tn*Dn) ? 1 : 0;
    k_offsets<<<1, 256>>>(out, write_aux);
    k_scatter<<<(Tn+255)/256, 256>>>();

    // ---- join: expert GEMMs need the converted weights ----
    cudaStreamWaitEvent(0, evJoin, 0);

    k_gemm<16,EPI_HALF,true,true><<<dim3(32, MAXROWS/128, 2), 256, GEMM_SMEM>>>(
        pXN2h, Dn, pWgeh, pWueh, pWueh, (long)HIDn*Dn, Dn, pGh, pUh, pUh, HIDn,
        nullptr, nullptr);

    k_silumul<<<(MAXROWS*(HIDn/4))/256, 256>>>();

    k_gemm<64,EPI_DOWN,false,true><<<dim3(8, MAXROWS/128, 1), 256, GEMM_SMEM>>>(
        pHh, HIDn, pWdeh, pWdeh, pWdeh, (long)Dn*HIDn, HIDn, out, out, out, Dn,
        nullptr, nullptr);
}

// round 10
// speedup vs baseline: 1.8429x; 1.0005x over previous
#include <cuda_runtime.h>
#include <cuda_fp16.h>
#include <math.h>
#include <stdint.h>

// Problem constants
#define Bn 2
#define Sn 1024
#define Dn 1024
#define NHn 16
#define HDn 64
#define En 8
#define HIDn 4096
#define Tn (Bn*Sn)          // 2048 tokens
#define MAXROWS 5248        // >= 4096 assignments + 8*127 padding, mult of 128

// ---------------- scratch (static device globals; no allocation) -------------
static __device__ __half g_XNh [Tn*Dn];
static __device__ float  g_Vb  [Tn*Dn];
static __device__ __half g_Qh  [Tn*Dn];
static __device__ __half g_Kh  [Tn*Dn];
static __device__ __half g_Vt  [(size_t)Bn*NHn*HDn*Sn];
static __device__ __half g_ATTh[Tn*Dn];
static __device__ float  g_Hb  [Tn*Dn];
static __device__ float  g_XN2 [Tn*Dn];
static __device__ __half g_XN2h[Tn*Dn];
static __device__ __half g_GBh [(size_t)MAXROWS*HIDn];
static __device__ __half g_UBh [(size_t)MAXROWS*HIDn];
static __device__ __half g_Hh  [(size_t)MAXROWS*HIDn];
// fp16 weights
static __device__ __half g_Wqh[Dn*Dn];
static __device__ __half g_Wkh[Dn*Dn];
static __device__ __half g_Wvh[Dn*Dn];
static __device__ __half g_Woh[Dn*Dn];
static __device__ __half g_Wgeh[(size_t)En*HIDn*Dn];
static __device__ __half g_Wueh[(size_t)En*HIDn*Dn];
static __device__ __half g_Wdeh[(size_t)En*Dn*HIDn];
// routing
static __device__ int   g_cnt[En];
static __device__ int   g_cursor[En];
static __device__ int   g_rowtok[MAXROWS];
static __device__ int   g_rowexp[MAXROWS];
static __device__ float g_rowgate[MAXROWS];
static __device__ int   g_totalrows;
static __device__ float g_gsum[En];
static __device__ float g_psum[En];
static __device__ int   g_expid[Tn*2];
static __device__ float g_gateval[Tn*2];

// ======================= PTX helpers =========================================
static __device__ __forceinline__ uint32_t smem_u32_(const void* p){
    uint32_t a;
    asm("{ .reg .u64 t; cvta.to.shared.u64 t, %1; cvt.u32.u64 %0, t; }"
        : "=r"(a) : "l"(p));
    return a;
}

#define LDSM_X4(r0,r1,r2,r3,addr) \
    asm volatile("ldmatrix.sync.aligned.m8n8.x4.shared.b16 {%0,%1,%2,%3}, [%4];" \
        : "=r"(r0),"=r"(r1),"=r"(r2),"=r"(r3) : "r"(addr))

#define MMA16816(c,a,b) \
    asm volatile("mma.sync.aligned.m16n8k16.row.col.f32.f16.f16.f32 " \
        "{%0,%1,%2,%3}, {%4,%5,%6,%7}, {%8,%9}, {%0,%1,%2,%3};" \
        : "+f"((c)[0]),"+f"((c)[1]),"+f"((c)[2]),"+f"((c)[3]) \
        : "r"((a)[0]),"r"((a)[1]),"r"((a)[2]),"r"((a)[3]), \
          "r"((b)[0]),"r"((b)[1]))

#define CP_COMMIT() asm volatile("cp.async.commit_group;" ::: "memory")
#define CP_WAIT(N)  asm volatile("cp.async.wait_group %0;" :: "n"(N) : "memory")

static __device__ __forceinline__ void cp16_(uint32_t dst, const void* src, int srcsize){
    asm volatile("cp.async.cg.shared.global [%0], [%1], 16, %2;"
        :: "r"(dst), "l"((unsigned long long)__cvta_generic_to_global(src)),
           "r"(srcsize) : "memory");
}

// ============================== small kernels ================================
__global__ void k_reset() {
    int i = threadIdx.x;
    if (i < En) { g_cnt[i] = 0; g_gsum[i] = 0.f; g_psum[i] = 0.f; }
}

static __device__ __forceinline__ void f2h_one_(const float4* s, uint2* d, int i){
    float4 v = s[i];
    __half2 h0 = __floats2half2_rn(v.x, v.y);
    __half2 h1 = __floats2half2_rn(v.z, v.w);
    uint2 o;
    o.x = *reinterpret_cast<uint32_t*>(&h0);
    o.y = *reinterpret_cast<uint32_t*>(&h1);
    d[i] = o;
}

__global__ void k_f2h2(const float4* __restrict__ s0, const float4* __restrict__ s1,
                       uint2* __restrict__ d0, uint2* __restrict__ d1, int n4){
    int i = blockIdx.x*blockDim.x + threadIdx.x;
    if (i >= n4) return;
    if (blockIdx.y == 0) f2h_one_(s0, d0, i);
    else                 f2h_one_(s1, d1, i);
}

__global__ void k_f2h4(const float4* __restrict__ s0, const float4* __restrict__ s1,
                       const float4* __restrict__ s2p, const float4* __restrict__ s3,
                       uint2* __restrict__ d0, uint2* __restrict__ d1,
                       uint2* __restrict__ d2, uint2* __restrict__ d3, int n4){
    int i = blockIdx.x*blockDim.x + threadIdx.x;
    if (i >= n4) return;
    switch (blockIdx.y){
        case 0: f2h_one_(s0, d0, i); break;
        case 1: f2h_one_(s1, d1, i); break;
        case 2: f2h_one_(s2p, d2, i); break;
        default: f2h_one_(s3, d3, i); break;
    }
}

__global__ void k_f2h(const float4* __restrict__ s, uint2* __restrict__ d, int n4){
    int i = blockIdx.x*blockDim.x + threadIdx.x;
    if (i >= n4) return;
    f2h_one_(s, d, i);
}

__global__ void k_rmsnorm(const float* __restrict__ x, const float* __restrict__ w,
                          float* __restrict__ y, __half* __restrict__ yh) {
    int t = blockIdx.x;
    const float* xr = x + (size_t)t * Dn;
    int base = threadIdx.x * 4;
    float4 xv = *(const float4*)(xr + base);
    float ss = xv.x*xv.x + xv.y*xv.y + xv.z*xv.z + xv.w*xv.w;
    #pragma unroll
    for (int o = 16; o; o >>= 1) ss += __shfl_xor_sync(0xffffffffu, ss, o);
    __shared__ float ws[8];
    if ((threadIdx.x & 31) == 0) ws[threadIdx.x >> 5] = ss;
    __syncthreads();
    float tot = ws[0]+ws[1]+ws[2]+ws[3]+ws[4]+ws[5]+ws[6]+ws[7];
    float sc = rsqrtf(tot * (1.f/(float)Dn) + 1e-6f);
    float4 wv = *(const float4*)(w + base);
    float4 o4;
    o4.x = wv.x*xv.x*sc; o4.y = wv.y*xv.y*sc;
    o4.z = wv.z*xv.z*sc; o4.w = wv.w*xv.w*sc;
    if (y) *(float4*)(y + (size_t)t*Dn + base) = o4;
    __half2 h0 = __floats2half2_rn(o4.x, o4.y);
    __half2 h1 = __floats2half2_rn(o4.z, o4.w);
    uint2 ho;
    ho.x = *reinterpret_cast<uint32_t*>(&h0);
    ho.y = *reinterpret_cast<uint32_t*>(&h1);
    *(uint2*)(yh + (size_t)t*Dn + base) = ho;
}

// ===================== mma.sync GEMM (HMMA tensor path) ======================
#define EPI_PLAIN 0
#define EPI_RESID 1
#define EPI_DOWN  2
#define EPI_HALF  3
#define EPI_ROPE  4
#define GEMM_SMEM (3*32768)

template<int NITER, int EPI, bool GATHER, bool ESEL, bool ZSPLIT=false>
__global__ __launch_bounds__(256)
void k_gemm(const __half* __restrict__ A0, int lda,
            const __half* __restrict__ B0, const __half* __restrict__ B1,
            const __half* __restrict__ B2,
            long bstride, int ldb,
            void* __restrict__ C0v, void* __restrict__ C1v, void* __restrict__ C2v,
            int ldc,
            const float* __restrict__ resid, float* __restrict__ Cdual)
{
    constexpr int S = 3;
    int mt = blockIdx.y, nt = blockIdx.x;
    if (ESEL && mt*128 >= g_totalrows) return;
    const __half* Bh = ZSPLIT ? B0
        : ((blockIdx.z==0) ? B0 : ((blockIdx.z==1) ? B1 : B2));
    void* Cv = ZSPLIT ? C0v
        : ((blockIdx.z==0) ? C0v : ((blockIdx.z==1) ? C1v : C2v));
    if (ESEL) Bh += (long)g_rowexp[mt*128] * bstride;
    long koff = ZSPLIT ? (long)blockIdx.z * (NITER*64) : 0;

    extern __shared__ __align__(128) char sm_[];
    uint32_t sbase = smem_u32_(sm_);

    int tid = threadIdx.x, lane = tid & 31, wid = tid >> 5;
    int warp_m = wid & 3, warp_n = wid >> 2;

    int lrow = tid >> 1;
    int lc0  = (tid & 1) * 4;
    const __half* asrc;
    bool avalid = true;
    if (GATHER){
        int tok = g_rowtok[mt*128 + lrow];
        avalid = (tok >= 0);
        asrc = A0 + (avalid ? (size_t)tok * lda : 0);
    } else {
        asrc = A0 + (size_t)(mt*128 + lrow) * lda;
    }
    asrc += koff;
    const __half* bsrc = Bh + (size_t)(nt*128 + lrow) * ldb + koff;
    int asz = avalid ? 16 : 0;
    uint32_t arow_s = sbase + lrow*128;
    uint32_t brow_s = arow_s + 16384;

    auto stg = [&](int it){
        int stage = it % S;
        uint32_t so = (uint32_t)stage * 32768u;
        const char* ag = (const char*)(asrc + it*64);
        const char* bg = (const char*)(bsrc + it*64);
        #pragma unroll
        for (int i = 0; i < 4; i++){
            int c = lc0 + i;
            uint32_t sw = (uint32_t)((c ^ (lrow & 7)) * 16);
            cp16_(arow_s + so + sw, ag + c*16, asz);
            cp16_(brow_s + so + sw, bg + c*16, 16);
        }
    };

    float acc[2][8][4];
    #pragma unroll
    for (int i=0;i<2;i++)
        #pragma unroll
        for (int j=0;j<8;j++)
            #pragma unroll
            for (int k=0;k<4;k++) acc[i][j][k]=0.f;

    #pragma unroll
    for (int it = 0; it < S-1; it++){ stg(it); CP_COMMIT(); }

    int a_rlo = (lane & 15);
    int a_chk = (lane >> 4);
    int b_rlo = (lane & 7) + ((lane & 16) ? 8 : 0);
    int b_chk = (lane >> 3) & 1;

    for (int it = 0; it < NITER; it++){
        CP_WAIT(S-2);
        __syncthreads();
        if (it + S-1 < NITER) stg(it + S-1);
        CP_COMMIT();

        uint32_t so = (uint32_t)(it % S) * 32768u;
        uint32_t abase = sbase + so;
        uint32_t bbase = abase + 16384;

        #pragma unroll
        for (int ks = 0; ks < 4; ks++){
            uint32_t a[2][4];
            #pragma unroll
            for (int mtile = 0; mtile < 2; mtile++){
                int row = warp_m*32 + mtile*16 + a_rlo;
                int chunk = 2*ks + a_chk;
                uint32_t addr = abase + row*128 + ((chunk ^ (row & 7)) * 16);
                LDSM_X4(a[mtile][0], a[mtile][1], a[mtile][2], a[mtile][3], addr);
            }
            uint32_t b[8][2];
            #pragma unroll
            for (int n2 = 0; n2 < 4; n2++){
                int row = warp_n*64 + n2*16 + b_rlo;
                int chunk = 2*ks + b_chk;
                uint32_t addr = bbase + row*128 + ((chunk ^ (row & 7)) * 16);
                uint32_t r0,r1,r2,r3;
                LDSM_X4(r0, r1, r2, r3, addr);
                b[2*n2][0]=r0; b[2*n2][1]=r1;
                b[2*n2+1][0]=r2; b[2*n2+1][1]=r3;
            }
            #pragma unroll
            for (int mtile = 0; mtile < 2; mtile++)
                #pragma unroll
                for (int n8 = 0; n8 < 8; n8++)
                    MMA16816(acc[mtile][n8], a[mtile], b[n8]);
        }
        __syncthreads();
    }

    // ---- epilogue ----
    int m0 = mt*128 + warp_m*32;
    int n0 = nt*128 + warp_n*64;
    int gq = lane >> 2, tq = lane & 3;
    #pragma unroll
    for (int mtile = 0; mtile < 2; mtile++){
        int r_lo = m0 + mtile*16 + gq;
        int r_hi = r_lo + 8;
        if (EPI == EPI_DOWN){
            float* C = (float*)Cv;
            int tok_lo = g_rowtok[r_lo], tok_hi = g_rowtok[r_hi];
            float gl = g_rowgate[r_lo], gh = g_rowgate[r_hi];
            #pragma unroll
            for (int n8 = 0; n8 < 8; n8++){
                int col = n0 + n8*8 + tq*2;
                if (tok_lo >= 0){
                    size_t o = (size_t)tok_lo*ldc + col;
                    atomicAdd(&C[o],   gl*acc[mtile][n8][0]);
                    atomicAdd(&C[o+1], gl*acc[mtile][n8][1]);
                }
                if (tok_hi >= 0){
                    size_t o = (size_t)tok_hi*ldc + col;
                    atomicAdd(&C[o],   gh*acc[mtile][n8][2]);
                    atomicAdd(&C[o+1], gh*acc[mtile][n8][3]);
                }
            }
        } else if (EPI == EPI_RESID){
            float* C = (float*)Cv;
            #pragma unroll
            for (int n8 = 0; n8 < 8; n8++){
                int col = n0 + n8*8 + tq*2;
                size_t o_lo = (size_t)r_lo*ldc + col;
                size_t o_hi = (size_t)r_hi*ldc + col;
                float2 rv0 = *(const float2*)(resid + o_lo);
                float2 rv1 = *(const float2*)(resid + o_hi);
                float2 v0, v1;
                v0.x = acc[mtile][n8][0] + rv0.x;
                v0.y = acc[mtile][n8][1] + rv0.y;
                v1.x = acc[mtile][n8][2] + rv1.x;
                v1.y = acc[mtile][n8][3] + rv1.y;
                *(float2*)(C + o_lo) = v0;
                *(float2*)(C + o_hi) = v1;
                *(float2*)(Cdual + o_lo) = v0;
                *(float2*)(Cdual + o_hi) = v1;
            }
        } else if (EPI == EPI_HALF){
            __half* Ch = (__half*)Cv;
            #pragma unroll
            for (int n8 = 0; n8 < 8; n8++){
                int col = n0 + n8*8 + tq*2;
                __half2 v0 = __floats2half2_rn(acc[mtile][n8][0], acc[mtile][n8][1]);
                __half2 v1 = __floats2half2_rn(acc[mtile][n8][2], acc[mtile][n8][3]);
                *(__half2*)(Ch + (size_t)r_lo*ldc + col) = v0;
                *(__half2*)(Ch + (size_t)r_hi*ldc + col) = v1;
            }
        } else if (EPI == EPI_ROPE){
            if (blockIdx.z == 2){
                // V: plain fp32 store
                float* C = (float*)Cv;
                #pragma unroll
                for (int n8 = 0; n8 < 8; n8++){
                    int col = n0 + n8*8 + tq*2;
                    float2 v0, v1;
                    v0.x = acc[mtile][n8][0]; v0.y = acc[mtile][n8][1];
                    v1.x = acc[mtile][n8][2]; v1.y = acc[mtile][n8][3];
                    *(float2*)(C + (size_t)r_lo*ldc + col) = v0;
                    *(float2*)(C + (size_t)r_hi*ldc + col) = v1;
                }
            } else {
                // Q/K: in-register RoPE (warp covers exactly one head; dim
                // partner i+32 lives in acc[..][n8+4]) then fp16 store
                __half* Ch = (__half*)Cv;
                int s_lo = r_lo & (Sn-1);
                int s_hi = r_hi & (Sn-1);
                #pragma unroll
                for (int n8 = 0; n8 < 4; n8++){
                    int col = n0 + n8*8 + tq*2;
                    int i0 = col & 63;                      // < 32
                    float inv0 = powf(10000.f, (float)(-2*i0)   * (1.f/64.f));
                    float inv1 = powf(10000.f, (float)(-2*(i0+1)) * (1.f/64.f));
                    float c0l,s0l,c1l,s1l,c0h,s0h,c1h,s1h;
                    sincosf((float)s_lo*inv0, &s0l, &c0l);
                    sincosf((float)s_lo*inv1, &s1l, &c1l);
                    sincosf((float)s_hi*inv0, &s0h, &c0h);
                    sincosf((float)s_hi*inv1, &s1h, &c1h);
                    float a0 = acc[mtile][n8][0],   a1 = acc[mtile][n8][1];
                    float b0 = acc[mtile][n8+4][0], b1 = acc[mtile][n8+4][1];
                    float a2 = acc[mtile][n8][2],   a3 = acc[mtile][n8][3];
                    float b2 = acc[mtile][n8+4][2], b3 = acc[mtile][n8+4][3];
                    __half2 lo_a = __floats2half2_rn(a0*c0l - b0*s0l, a1*c1l - b1*s1l);
                    __half2 lo_b = __floats2half2_rn(b0*c0l + a0*s0l, b1*c1l + a1*s1l);
                    __half2 hi_a = __floats2half2_rn(a2*c0h - b2*s0h, a3*c1h - b3*s1h);
                    __half2 hi_b = __floats2half2_rn(b2*c0h + a2*s0h, b3*c1h + a3*s1h);
                    *(__half2*)(Ch + (size_t)r_lo*ldc + col)      = lo_a;
                    *(__half2*)(Ch + (size_t)r_lo*ldc + col + 32) = lo_b;
                    *(__half2*)(Ch + (size_t)r_hi*ldc + col)      = hi_a;
                    *(__half2*)(Ch + (size_t)r_hi*ldc + col + 32) = hi_b;
                }
            }
        } else {
            float* C = (float*)Cv;
            #pragma unroll
            for (int n8 = 0; n8 < 8; n8++){
                int col = n0 + n8*8 + tq*2;
                float2 v0, v1;
                v0.x = acc[mtile][n8][0]; v0.y = acc[mtile][n8][1];
                v1.x = acc[mtile][n8][2]; v1.y = acc[mtile][n8][3];
                *(float2*)(C + (size_t)r_lo*ldc + col) = v0;
                *(float2*)(C + (size_t)r_hi*ldc + col) = v1;
            }
        }
    }
}

// ============ V transpose: fp32 [t][h*64+d] -> fp16 Vt[bh][d][s] =============
__global__ void k_vtrans(const float* __restrict__ V, __half* __restrict__ Vt)
{
    __shared__ float ts[64][65];
    int bh = blockIdx.x, st = blockIdx.y;
    int b = bh >> 4, h = bh & 15;
    int tid = threadIdx.x;                 // 128 threads
    int row = tid >> 1, c0 = (tid & 1) * 32;
    const float4* src = (const float4*)(V + ((size_t)(b*Sn + st*64 + row))*Dn
                                          + h*HDn + c0);
    #pragma unroll
    for (int i = 0; i < 8; i++){
        float4 v = src[i];
        ts[row][c0 + 4*i + 0] = v.x;
        ts[row][c0 + 4*i + 1] = v.y;
        ts[row][c0 + 4*i + 2] = v.z;
        ts[row][c0 + 4*i + 3] = v.w;
    }
    __syncthreads();
    __half* dst = Vt + ((size_t)bh*HDn + row)*Sn + st*64 + c0;
    #pragma unroll
    for (int i = 0; i < 32; i += 2){
        __half2 hv = __floats2half2_rn(ts[c0+i][row], ts[c0+i+1][row]);
        *(__half2*)(dst + i) = hv;
    }
}

// ================= HMMA flash attention (m16n8k16) ===========================
__global__ __launch_bounds__(128)
void k_attn_mma(const __half* __restrict__ Qh, const __half* __restrict__ Kh,
                const __half* __restrict__ Vt, __half* __restrict__ O)
{
    __shared__ __align__(128) char sm[3*8192];
    uint32_t qs = smem_u32_(sm);
    uint32_t ks = qs + 8192;
    uint32_t vs = qs + 16384;

    int bh = blockIdx.x;
    int qt = blockIdx.y;
    int b = bh >> 4, h = bh & 15;
    int tid = threadIdx.x, lane = tid & 31, wid = tid >> 5;
    int q0 = qt*64;

    int srow = tid >> 1, sc0 = (tid & 1) * 4;
    int gq = lane >> 2, tq = lane & 3;
    int a_rlo = lane & 15, a_chk = lane >> 4;
    int b_rlo = (lane & 7) + ((lane & 16) ? 8 : 0);
    int b_chk = (lane >> 3) & 1;

    {
        const uint4* src = (const uint4*)(Qh + ((size_t)(b*Sn + q0 + srow))*Dn + h*HDn);
        #pragma unroll
        for (int i = 0; i < 4; i++){
            int c = sc0 + i;
            *(uint4*)(sm + srow*128 + ((c ^ (srow & 7)) * 16)) = src[c];
        }
    }
    __syncthreads();

    uint32_t qa[4][4];
    #pragma unroll
    for (int kc = 0; kc < 4; kc++){
        int row = wid*16 + a_rlo;
        int chunk = kc*2 + a_chk;
        uint32_t addr = qs + row*128 + ((chunk ^ (row & 7)) * 16);
        LDSM_X4(qa[kc][0], qa[kc][1], qa[kc][2], qa[kc][3], addr);
    }

    float o_[8][4];
    #pragma unroll
    for (int j=0;j<8;j++)
        #pragma unroll
        for (int k=0;k<4;k++) o_[j][k]=0.f;
    float m_lo = -1e30f, m_hi = -1e30f, l_lo = 0.f, l_hi = 0.f;

    for (int kt = 0; kt <= qt; kt++){
        {
            const uint4* ksrc = (const uint4*)(Kh + ((size_t)(b*Sn + kt*64 + srow))*Dn + h*HDn);
            const uint4* vsrc = (const uint4*)(Vt + ((size_t)bh*HDn + srow)*Sn + kt*64);
            #pragma unroll
            for (int i = 0; i < 4; i++){
                int c = sc0 + i;
                uint32_t sw = (uint32_t)((c ^ (srow & 7)) * 16);
                *(uint4*)(sm + 8192  + srow*128 + sw) = ksrc[c];
                *(uint4*)(sm + 16384 + srow*128 + sw) = vsrc[c];
            }
        }
        __syncthreads();

        float s_[8][4];
        #pragma unroll
        for (int j=0;j<8;j++)
            #pragma unroll
            for (int k=0;k<4;k++) s_[j][k]=0.f;
        #pragma unroll
        for (int kc = 0; kc < 4; kc++){
            uint32_t kb[8][2];
            #pragma unroll
            for (int n2 = 0; n2 < 4; n2++){
                int row = n2*16 + b_rlo;
                int chunk = kc*2 + b_chk;
                uint32_t addr = ks + row*128 + ((chunk ^ (row & 7)) * 16);
                uint32_t r0,r1,r2,r3;
                LDSM_X4(r0, r1, r2, r3, addr);
                kb[2*n2][0]=r0; kb[2*n2][1]=r1;
                kb[2*n2+1][0]=r2; kb[2*n2+1][1]=r3;
            }
            #pragma unroll
            for (int j = 0; j < 8; j++)
                MMA16816(s_[j], qa[kc], kb[j]);
        }

        int row_lo = q0 + wid*16 + gq;
        int row_hi = row_lo + 8;
        #pragma unroll
        for (int j = 0; j < 8; j++){
            int c0 = kt*64 + j*8 + tq*2;
            int c1 = c0 + 1;
            s_[j][0] = (c0 <= row_lo) ? s_[j][0]*0.125f : -1e30f;
            s_[j][1] = (c1 <= row_lo) ? s_[j][1]*0.125f : -1e30f;
            s_[j][2] = (c0 <= row_hi) ? s_[j][2]*0.125f : -1e30f;
            s_[j][3] = (c1 <= row_hi) ? s_[j][3]*0.125f : -1e30f;
        }

        float tm_lo = -1e30f, tm_hi = -1e30f;
        #pragma unroll
        for (int j = 0; j < 8; j++){
            tm_lo = fmaxf(tm_lo, fmaxf(s_[j][0], s_[j][1]));
            tm_hi = fmaxf(tm_hi, fmaxf(s_[j][2], s_[j][3]));
        }
        tm_lo = fmaxf(tm_lo, __shfl_xor_sync(0xffffffffu, tm_lo, 1));
        tm_lo = fmaxf(tm_lo, __shfl_xor_sync(0xffffffffu, tm_lo, 2));
        tm_hi = fmaxf(tm_hi, __shfl_xor_sync(0xffffffffu, tm_hi, 1));
        tm_hi = fmaxf(tm_hi, __shfl_xor_sync(0xffffffffu, tm_hi, 2));
        float mn_lo = fmaxf(m_lo, tm_lo);
        float mn_hi = fmaxf(m_hi, tm_hi);
        float corr_lo = __expf(m_lo - mn_lo);
        float corr_hi = __expf(m_hi - mn_hi);
        float rs_lo = 0.f, rs_hi = 0.f;
        #pragma unroll
        for (int j = 0; j < 8; j++){
            s_[j][0] = __expf(s_[j][0] - mn_lo);
            s_[j][1] = __expf(s_[j][1] - mn_lo);
            s_[j][2] = __expf(s_[j][2] - mn_hi);
            s_[j][3] = __expf(s_[j][3] - mn_hi);
            rs_lo += s_[j][0] + s_[j][1];
            rs_hi += s_[j][2] + s_[j][3];
        }
        rs_lo += __shfl_xor_sync(0xffffffffu, rs_lo, 1);
        rs_lo += __shfl_xor_sync(0xffffffffu, rs_lo, 2);
        rs_hi += __shfl_xor_sync(0xffffffffu, rs_hi, 1);
        rs_hi += __shfl_xor_sync(0xffffffffu, rs_hi, 2);
        l_lo = l_lo*corr_lo + rs_lo;
        l_hi = l_hi*corr_hi + rs_hi;
        m_lo = mn_lo; m_hi = mn_hi;
        #pragma unroll
        for (int j = 0; j < 8; j++){
            o_[j][0] *= corr_lo; o_[j][1] *= corr_lo;
            o_[j][2] *= corr_hi; o_[j][3] *= corr_hi;
        }

        uint32_t pa[4][4];
        #pragma unroll
        for (int kc = 0; kc < 4; kc++){
            __half2 h0 = __floats2half2_rn(s_[2*kc][0],   s_[2*kc][1]);
            __half2 h1 = __floats2half2_rn(s_[2*kc][2],   s_[2*kc][3]);
            __half2 h2 = __floats2half2_rn(s_[2*kc+1][0], s_[2*kc+1][1]);
            __half2 h3 = __floats2half2_rn(s_[2*kc+1][2], s_[2*kc+1][3]);
            pa[kc][0] = *reinterpret_cast<uint32_t*>(&h0);
            pa[kc][1] = *reinterpret_cast<uint32_t*>(&h1);
            pa[kc][2] = *reinterpret_cast<uint32_t*>(&h2);
            pa[kc][3] = *reinterpret_cast<uint32_t*>(&h3);
        }

        #pragma unroll
        for (int kc = 0; kc < 4; kc++){
            uint32_t vb[8][2];
            #pragma unroll
            for (int n2 = 0; n2 < 4; n2++){
                int row = n2*16 + b_rlo;
                int chunk = kc*2 + b_chk;
                uint32_t addr = vs + row*128 + ((chunk ^ (row & 7)) * 16);
                uint32_t r0,r1,r2,r3;
                LDSM_X4(r0, r1, r2, r3, addr);
                vb[2*n2][0]=r0; vb[2*n2][1]=r1;
                vb[2*n2+1][0]=r2; vb[2*n2+1][1]=r3;
            }
            #pragma unroll
            for (int j = 0; j < 8; j++)
                MMA16816(o_[j], pa[kc], vb[j]);
        }
        __syncthreads();
    }

    float inv_lo = 1.f/l_lo, inv_hi = 1.f/l_hi;
    int row_lo = q0 + wid*16 + gq;
    int row_hi = row_lo + 8;
    #pragma unroll
    for (int j = 0; j < 8; j++){
        int col = j*8 + tq*2;
        __half2 v0 = __floats2half2_rn(o_[j][0]*inv_lo, o_[j][1]*inv_lo);
        __half2 v1 = __floats2half2_rn(o_[j][2]*inv_hi, o_[j][3]*inv_hi);
        *(__half2*)(O + ((size_t)(b*Sn + row_lo))*Dn + h*HDn + col) = v0;
        *(__half2*)(O + ((size_t)(b*Sn + row_hi))*Dn + h*HDn + col) = v1;
    }
}

// =============================== gating / MoE ================================
__global__ void k_gate(const float* __restrict__ xn, const float* __restrict__ gw)
{
    int t = blockIdx.x;
    int w = threadIdx.x >> 5, lane = threadIdx.x & 31;
    const float* xr = xn + (size_t)t * Dn;
    const float* gr = gw + (size_t)w * Dn;
    float acc = 0.f;
    for (int d = lane; d < Dn; d += 32) acc = fmaf(xr[d], gr[d], acc);
    #pragma unroll
    for (int o=16;o;o>>=1) acc += __shfl_xor_sync(0xffffffffu, acc, o);
    __shared__ float lg[En];
    if (lane == 0) lg[w] = acc;
    __syncthreads();
    if (threadIdx.x == 0){
        int i1 = 0;
        for (int e=1;e<En;e++) if (lg[e] > lg[i1]) i1 = e;
        int i2 = -1;
        for (int e=0;e<En;e++){
            if (e == i1) continue;
            if (i2 < 0 || lg[e] > lg[i2]) i2 = e;
        }
        float l1 = lg[i1], l2 = lg[i2];
        float e2 = expf(l2 - l1);
        float inv = 1.f/(1.f + e2);
        float gv1 = inv, gv2 = e2*inv;
        g_expid[t*2]   = i1; g_expid[t*2+1]   = i2;
        g_gateval[t*2] = gv1; g_gateval[t*2+1] = gv2;
        atomicAdd(&g_cnt[i1], 1); atomicAdd(&g_cnt[i2], 1);
        atomicAdd(&g_gsum[i1], gv1); atomicAdd(&g_gsum[i2], gv2);
        float mx = lg[0];
        for (int e=1;e<En;e++) mx = fmaxf(mx, lg[e]);
        float pe[En]; float se = 0.f;
        for (int e=0;e<En;e++){ pe[e] = expf(lg[e]-mx); se += pe[e]; }
        float pinv = 1.f/se;
        for (int e=0;e<En;e++) atomicAdd(&g_psum[e], pe[e]*pinv);
    }
}

__global__ void k_offsets(float* __restrict__ out, int write_aux)
{
    __shared__ int soff[En+1];
    if (threadIdx.x == 0){
        int tot = 0;
        for (int e=0;e<En;e++){
            soff[e] = tot;
            g_cursor[e] = tot;
            tot += ((g_cnt[e] + 127) >> 7) << 7;
        }
        soff[En] = tot;
        g_totalrows = tot;
        if (write_aux){
            float sacc = 0.f;
            for (int e=0;e<En;e++) sacc += g_gsum[e]*g_psum[e];
            out[(size_t)Tn*Dn] = (float)En * sacc / ((float)Tn*(float)Tn);
        }
    }
    __syncthreads();
    int tot = soff[En];
    for (int r = threadIdx.x; r < tot; r += blockDim.x){
        int e = 0;
        while (e+1 < En && r >= soff[e+1]) e++;
        g_rowexp[r] = e;
        g_rowtok[r] = -1;
    }
}

__global__ void k_scatter()
{
    int t = blockIdx.x*blockDim.x + threadIdx.x;
    if (t >= Tn) return;
    #pragma unroll
    for (int k=0;k<2;k++){
        int e = g_expid[t*2+k];
        int pos = atomicAdd(&g_cursor[e], 1);
        g_rowtok[pos] = t;
        g_rowgate[pos] = g_gateval[t*2+k];
    }
}

// H = silu(G) * U, fp16 in -> fp16 out
__global__ void k_silumul()
{
    size_t i4 = ((size_t)blockIdx.x*blockDim.x + threadIdx.x) * 4;
    size_t n = (size_t)g_totalrows * HIDn;
    if (i4 >= n) return;
    uint2 gp = *(uint2*)&g_GBh[i4];
    uint2 up = *(uint2*)&g_UBh[i4];
    __half2 g0 = *reinterpret_cast<__half2*>(&gp.x);
    __half2 g1 = *reinterpret_cast<__half2*>(&gp.y);
    __half2 u0 = *reinterpret_cast<__half2*>(&up.x);
    __half2 u1 = *reinterpret_cast<__half2*>(&up.y);
    float gx = __low2float(g0),  gy = __high2float(g0);
    float gz = __low2float(g1),  gw_ = __high2float(g1);
    float ux = __low2float(u0),  uy = __high2float(u0);
    float uz = __low2float(u1),  uw = __high2float(u1);
    float a = (gx / (1.f + __expf(-gx))) * ux;
    float b = (gy / (1.f + __expf(-gy))) * uy;
    float c = (gz / (1.f + __expf(-gz))) * uz;
    float d = (gw_ / (1.f + __expf(-gw_))) * uw;
    __half2 h0 = __floats2half2_rn(a, b);
    __half2 h1 = __floats2half2_rn(c, d);
    uint2 o;
    o.x = *reinterpret_cast<uint32_t*>(&h0);
    o.y = *reinterpret_cast<uint32_t*>(&h1);
    *(uint2*)&g_Hh[i4] = o;
}

// ---------------------------------------------------------------------------
extern "C" void kernel_launch(void* const* d_in, const int* in_sizes, int n_in,
                              void* d_out, int out_size)
{
    (void)in_sizes; (void)n_in;
    const float* x   = (const float*)d_in[0];
    const float* wq  = (const float*)d_in[1];
    const float* wk  = (const float*)d_in[2];
    const float* wv  = (const float*)d_in[3];
    const float* wo  = (const float*)d_in[4];
    const float* anw = (const float*)d_in[5];
    const float* fnw = (const float*)d_in[6];
    const float* gw  = (const float*)d_in[7];
    const float* wge = (const float*)d_in[8];
    const float* wue = (const float*)d_in[9];
    const float* wde = (const float*)d_in[10];
    float* out = (float*)d_out;

    float *pV,*pH,*pXN2;
    __half *pXNh,*pATTh,*pXN2h,*pHh,*pGh,*pUh,*pQhh,*pKhh,*pVt;
    __half *pWqh,*pWkh,*pWvh,*pWoh,*pWgeh,*pWueh,*pWdeh;
    cudaGetSymbolAddress((void**)&pV,    g_Vb);
    cudaGetSymbolAddress((void**)&pH,    g_Hb);
    cudaGetSymbolAddress((void**)&pXN2,  g_XN2);
    cudaGetSymbolAddress((void**)&pGh,   g_GBh);
    cudaGetSymbolAddress((void**)&pUh,   g_UBh);
    cudaGetSymbolAddress((void**)&pXNh,  g_XNh);
    cudaGetSymbolAddress((void**)&pATTh, g_ATTh);
    cudaGetSymbolAddress((void**)&pXN2h, g_XN2h);
    cudaGetSymbolAddress((void**)&pHh,   g_Hh);
    cudaGetSymbolAddress((void**)&pQhh,  g_Qh);
    cudaGetSymbolAddress((void**)&pKhh,  g_Kh);
    cudaGetSymbolAddress((void**)&pVt,   g_Vt);
    cudaGetSymbolAddress((void**)&pWqh,  g_Wqh);
    cudaGetSymbolAddress((void**)&pWkh,  g_Wkh);
    cudaGetSymbolAddress((void**)&pWvh,  g_Wvh);
    cudaGetSymbolAddress((void**)&pWoh,  g_Woh);
    cudaGetSymbolAddress((void**)&pWgeh, g_Wgeh);
    cudaGetSymbolAddress((void**)&pWueh, g_Wueh);
    cudaGetSymbolAddress((void**)&pWdeh, g_Wdeh);

    cudaFuncSetAttribute(k_gemm<16,EPI_ROPE,false,false>,
                         cudaFuncAttributeMaxDynamicSharedMemorySize, GEMM_SMEM);
    cudaFuncSetAttribute(k_gemm<16,EPI_RESID,false,false>,
                         cudaFuncAttributeMaxDynamicSharedMemorySize, GEMM_SMEM);
    cudaFuncSetAttribute(k_gemm<16,EPI_HALF,true,true>,
                         cudaFuncAttributeMaxDynamicSharedMemorySize, GEMM_SMEM);
    cudaFuncSetAttribute(k_gemm<32,EPI_DOWN,false,true,true>,
                         cudaFuncAttributeMaxDynamicSharedMemorySize, GEMM_SMEM);

    // side stream for expert-weight conversion, overlapped with attention path
    static cudaStream_t s2 = nullptr;
    static cudaEvent_t evFork = nullptr, evJoin = nullptr;
    if (!s2){
        cudaStreamCreateWithFlags(&s2, cudaStreamNonBlocking);
        cudaEventCreateWithFlags(&evFork, cudaEventDisableTiming);
        cudaEventCreateWithFlags(&evJoin, cudaEventDisableTiming);
    }

    k_reset<<<1, 32>>>();

    // ---- fork: expert weight conversions on s2 ----
    cudaEventRecord(evFork, 0);
    cudaStreamWaitEvent(s2, evFork, 0);
    {
        int ne4 = En*HIDn*(Dn/4), blk = 256, g2 = (ne4+blk-1)/blk;
        k_f2h2<<<dim3(g2,2), blk, 0, s2>>>((const float4*)wge, (const float4*)wue,
                                           (uint2*)pWgeh, (uint2*)pWueh, ne4);
        k_f2h<<<g2, blk, 0, s2>>>((const float4*)wde, (uint2*)pWdeh, ne4);
    }
    cudaEventRecord(evJoin, s2);

    // ---- main stream: attention path ----
    {
        int n4 = Dn*Dn/4, blk = 256, g1 = (n4+blk-1)/blk;
        k_f2h4<<<dim3(g1,4), blk>>>((const float4*)wq, (const float4*)wk,
                                    (const float4*)wv, (const float4*)wo,
                                    (uint2*)pWqh, (uint2*)pWkh,
                                    (uint2*)pWvh, (uint2*)pWoh, n4);
    }

    k_rmsnorm<<<Tn, 256>>>(x, anw, nullptr, pXNh);

    // QKV GEMM with fused RoPE: Q/K -> fp16 (rotated), V -> fp32
    k_gemm<16,EPI_ROPE,false,false><<<dim3(8,16,3), 256, GEMM_SMEM>>>(
        pXNh, Dn, pWqh, pWkh, pWvh, 0, Dn, pQhh, pKhh, pV, Dn, nullptr, nullptr);

    // V -> transposed fp16
    k_vtrans<<<dim3(Bn*NHn, Sn/64), 128>>>(pV, pVt);

    // HMMA flash attention
    k_attn_mma<<<dim3(Bn*NHn, Sn/64), 128>>>(pQhh, pKhh, pVt, pATTh);

    k_gemm<16,EPI_RESID,false,false><<<dim3(8,16,1), 256, GEMM_SMEM>>>(
        pATTh, Dn, pWoh, pWoh, pWoh, 0, Dn, pH, pH, pH, Dn, x, out);

    k_rmsnorm<<<Tn, 256>>>(pH, fnw, pXN2, pXN2h);

    k_gate<<<Tn, 256>>>(pXN2, gw);
    int write_aux = (out_size > Tn*Dn) ? 1 : 0;
    k_offsets<<<1, 256>>>(out, write_aux);
    k_scatter<<<(Tn+255)/256, 256>>>();

    // ---- join: expert GEMMs need the converted weights ----
    cudaStreamWaitEvent(0, evJoin, 0);

    k_gemm<16,EPI_HALF,true,true><<<dim3(32, MAXROWS/128, 2), 256, GEMM_SMEM>>>(
        pXN2h, Dn, pWgeh, pWueh, pWueh, (long)HIDn*Dn, Dn, pGh, pUh, pUh, HIDn,
        nullptr, nullptr);

    k_silumul<<<(MAXROWS*(HIDn/4))/256, 256>>>();

    // down GEMM: split-K x2 (atomics accumulate across splits)
    k_gemm<32,EPI_DOWN,false,true,true><<<dim3(8, MAXROWS/128, 2), 256, GEMM_SMEM>>>(
        pHh, HIDn, pWdeh, pWdeh, pWdeh, (long)Dn*HIDn, HIDn, out, out, out, Dn,
        nullptr, nullptr);
}